// round 6
// baseline (speedup 1.0000x reference)
#include <cuda_runtime.h>

#define N_NODES 50000
#define N_EDGES 800000
#define D 128
#define BN_EPS 1e-5f
#define TILE_R 32

// Persistent scratch (static device allocation — allowed; runtime alloc is not).
// __align__(16) is load-bearing: float4 loads/stores and RED.128 require it.
__device__ __align__(16) float g_z[N_NODES * D];    // current node features
__device__ __align__(16) float g_agg[N_NODES * D];  // edge aggregation buffer
__device__ float g_stats[2 * D];                    // column sum / sumsq for BN
__device__ int g_idx64;                             // 1 if edge_index is int64

// ---------------------------------------------------------------------------
// Probe edge_index dtype: int64 little-endian with values < 2^31 has all-zero
// odd 32-bit words. 64 odd words all zero => int64 (false-positive prob ~0).
// Deterministic function of the input; runs every call.
// ---------------------------------------------------------------------------
__global__ void probe_idx_kernel(const int* __restrict__ ei32) {
    int all_zero = 1;
#pragma unroll
    for (int i = 0; i < 64; i++)
        if (__ldg(&ei32[2 * i + 1]) != 0) all_zero = 0;
    g_idx64 = all_zero;
}

// ---------------------------------------------------------------------------
// Zero the aggregation buffer (+ BN stats, harmlessly re-zeroed per layer).
// ---------------------------------------------------------------------------
__global__ void zero_agg_kernel() {
    int i = blockIdx.x * blockDim.x + threadIdx.x;
    const int n4 = N_NODES * D / 4;   // 1,600,000
    if (i < n4) ((float4*)g_agg)[i] = make_float4(0.f, 0.f, 0.f, 0.f);
    if (blockIdx.x == 0 && threadIdx.x < 2 * D) g_stats[threadIdx.x] = 0.f;
}

// ---------------------------------------------------------------------------
// Edge aggregation: one warp per edge. Gather z[src] (L2-resident), scale by
// edge weight, vector-atomic scatter into agg[dst] (RED.128 -> L2).
// Handles both int32 and int64 edge_index via g_idx64; indices clamped so a
// wrong layout theory yields rel_err, never an illegal access.
// ---------------------------------------------------------------------------
__global__ void edge_kernel(const float* __restrict__ xin,
                            const float* __restrict__ ew,
                            const int* __restrict__ ei32,
                            int use_x) {
    int gw = (blockIdx.x * blockDim.x + threadIdx.x) >> 5;
    if (gw >= N_EDGES) return;
    int lane = threadIdx.x & 31;
    const float* z = use_x ? xin : g_z;

    int src, dst;
    if (g_idx64) {
        src = __ldg(&ei32[2 * gw]);                    // low word of int64
        dst = __ldg(&ei32[2 * N_EDGES + 2 * gw]);
    } else {
        src = __ldg(&ei32[gw]);
        dst = __ldg(&ei32[N_EDGES + gw]);
    }
    src = min(max(src, 0), N_NODES - 1);
    dst = min(max(dst, 0), N_NODES - 1);
    float w = __ldg(&ew[gw]);

    float4 v = ((const float4*)(z + (long long)src * D))[lane];
    v.x *= w; v.y *= w; v.z *= w; v.w *= w;

    float* p = g_agg + (long long)dst * D + lane * 4;   // 16B aligned
    asm volatile(
        "{\n\t"
        ".reg .u64 ga;\n\t"
        "cvta.to.global.u64 ga, %0;\n\t"
        "red.global.add.v4.f32 [ga], {%1, %2, %3, %4};\n\t"
        "}"
        :: "l"(p), "f"(v.x), "f"(v.y), "f"(v.z), "f"(v.w)
        : "memory");
}

// ---------------------------------------------------------------------------
// Fused GIN node update + 2-layer MLP for one layer:
//   h = (1+eps)*z + agg ; t = relu(h@W1+b1) ; z_new = relu(t@W2+b2)
// 32-row tile per block, 256 threads, weights staged in smem (one at a time,
// 96 KB total -> 2 blocks/SM). 4x4 register tiling, 2 FMA per LDS.
// ---------------------------------------------------------------------------
__global__ void mlp_kernel(const float* __restrict__ xin,
                           const float* __restrict__ W1s,
                           const float* __restrict__ b1s,
                           const float* __restrict__ W2s,
                           const float* __restrict__ b2s,
                           const float* __restrict__ epsp,
                           int layer) {
    extern __shared__ float sm[];
    float* sW = sm;            // 128*128 = 16384 floats
    float* sH = sm + 16384;    // 32*128  =  4096 floats
    float* sT = sm + 20480;    // 32*128  =  4096 floats

    const float* zin = (layer == 0) ? xin : g_z;
    const float* W1 = W1s + layer * D * D;
    const float* W2 = W2s + layer * D * D;
    const float* b1 = b1s + layer * D;
    const float* b2 = b2s + layer * D;
    const float onePlusEps = 1.f + __ldg(&epsp[layer]);

    int tid = threadIdx.x;
    int row0 = blockIdx.x * TILE_R;

    // Stage 1: build h tile in smem
    {
        const float4* z4 = (const float4*)zin;
        const float4* a4 = (const float4*)g_agg;
        float4* h4 = (float4*)sH;
#pragma unroll
        for (int t = 0; t < 4; t++) {
            int f = tid + t * 256;      // 0..1023
            int r = f >> 5;
            int c4 = f & 31;
            int gr = row0 + r;
            float4 hv = make_float4(0.f, 0.f, 0.f, 0.f);
            if (gr < N_NODES) {
                float4 zv = z4[gr * (D / 4) + c4];
                float4 av = a4[gr * (D / 4) + c4];
                hv.x = fmaf(onePlusEps, zv.x, av.x);
                hv.y = fmaf(onePlusEps, zv.y, av.y);
                hv.z = fmaf(onePlusEps, zv.z, av.z);
                hv.w = fmaf(onePlusEps, zv.w, av.w);
            }
            h4[f] = hv;
        }
    }
    // Load W1 into smem
    {
        const float4* w4 = (const float4*)W1;
        float4* s4 = (float4*)sW;
#pragma unroll
        for (int t = 0; t < 16; t++) s4[tid + t * 256] = w4[tid + t * 256];
    }
    __syncthreads();

    int ty = tid >> 5;   // 0..7
    int tx = tid & 31;   // 0..31

    // Stage 2: t = relu(h @ W1 + b1)
    {
        float acc[4][4];
#pragma unroll
        for (int i = 0; i < 4; i++)
#pragma unroll
            for (int j = 0; j < 4; j++) acc[i][j] = 0.f;

#pragma unroll 4
        for (int k = 0; k < D; k++) {
            float hv[4], wv[4];
#pragma unroll
            for (int i = 0; i < 4; i++) hv[i] = sH[(ty + 8 * i) * D + k];
#pragma unroll
            for (int j = 0; j < 4; j++) wv[j] = sW[k * D + tx + 32 * j];
#pragma unroll
            for (int i = 0; i < 4; i++)
#pragma unroll
                for (int j = 0; j < 4; j++) acc[i][j] = fmaf(hv[i], wv[j], acc[i][j]);
        }
#pragma unroll
        for (int j = 0; j < 4; j++) {
            float bv = __ldg(&b1[tx + 32 * j]);
#pragma unroll
            for (int i = 0; i < 4; i++)
                sT[(ty + 8 * i) * D + tx + 32 * j] = fmaxf(acc[i][j] + bv, 0.f);
        }
    }
    __syncthreads();

    // Load W2 into smem (overwrite W1 slot)
    {
        const float4* w4 = (const float4*)W2;
        float4* s4 = (float4*)sW;
#pragma unroll
        for (int t = 0; t < 16; t++) s4[tid + t * 256] = w4[tid + t * 256];
    }
    __syncthreads();

    // Stage 3: z_new = relu(t @ W2 + b2) -> g_z
    {
        float acc[4][4];
#pragma unroll
        for (int i = 0; i < 4; i++)
#pragma unroll
            for (int j = 0; j < 4; j++) acc[i][j] = 0.f;

#pragma unroll 4
        for (int k = 0; k < D; k++) {
            float hv[4], wv[4];
#pragma unroll
            for (int i = 0; i < 4; i++) hv[i] = sT[(ty + 8 * i) * D + k];
#pragma unroll
            for (int j = 0; j < 4; j++) wv[j] = sW[k * D + tx + 32 * j];
#pragma unroll
            for (int i = 0; i < 4; i++)
#pragma unroll
                for (int j = 0; j < 4; j++) acc[i][j] = fmaf(hv[i], wv[j], acc[i][j]);
        }
#pragma unroll
        for (int j = 0; j < 4; j++) {
            float bv = __ldg(&b2[tx + 32 * j]);
#pragma unroll
            for (int i = 0; i < 4; i++) {
                int gr = row0 + ty + 8 * i;
                if (gr < N_NODES)
                    g_z[gr * D + tx + 32 * j] = fmaxf(acc[i][j] + bv, 0.f);
            }
        }
    }
}

// ---------------------------------------------------------------------------
// BN statistics: per-column sum and sum-of-squares over all nodes.
// ---------------------------------------------------------------------------
__global__ void bn_stats_kernel() {
    int c = threadIdx.x;   // 128 threads = one column each
    float s = 0.f, ss = 0.f;
    for (int r = blockIdx.x; r < N_NODES; r += gridDim.x) {
        float v = g_z[r * D + c];
        s += v;
        ss += v * v;
    }
    atomicAdd(&g_stats[c], s);
    atomicAdd(&g_stats[D + c], ss);
}

// ---------------------------------------------------------------------------
// Fused BN-normalize (writes zn) + projection GEMM + PReLU (writes p).
// ---------------------------------------------------------------------------
__global__ void proj_kernel(const float* __restrict__ Wp,
                            const float* __restrict__ bp,
                            const float* __restrict__ gamma,
                            const float* __restrict__ beta,
                            const float* __restrict__ prelu_a,
                            float* __restrict__ out) {
    extern __shared__ float sm[];
    float* sW = sm;              // 16384
    float* sH = sm + 16384;      // 4096 (normalized tile)
    float* sScale = sm + 20480;  // 128
    float* sShift = sm + 20608;  // 128

    int tid = threadIdx.x;
    if (tid < D) {
        float mean = g_stats[tid] * (1.f / N_NODES);
        float var = g_stats[D + tid] * (1.f / N_NODES) - mean * mean;
        float rs = rsqrtf(var + BN_EPS);
        float sc = __ldg(&gamma[tid]) * rs;
        sScale[tid] = sc;
        sShift[tid] = __ldg(&beta[tid]) - mean * sc;
    }
    {
        const float4* w4 = (const float4*)Wp;
        float4* s4 = (float4*)sW;
#pragma unroll
        for (int t = 0; t < 16; t++) s4[tid + t * 256] = w4[tid + t * 256];
    }
    __syncthreads();

    int row0 = blockIdx.x * TILE_R;
    float* zn_out = out;                 // first N*D floats
    float* p_out = out + N_NODES * D;    // second N*D floats

    // Stage 1: normalize -> zn (global + smem)
    {
        const float4* z4 = (const float4*)g_z;
        float4* h4 = (float4*)sH;
#pragma unroll
        for (int t = 0; t < 4; t++) {
            int f = tid + t * 256;
            int r = f >> 5;
            int c4 = f & 31;
            int gr = row0 + r;
            float4 hv = make_float4(0.f, 0.f, 0.f, 0.f);
            if (gr < N_NODES) {
                float4 zv = z4[gr * (D / 4) + c4];
                int c = c4 * 4;
                hv.x = fmaf(zv.x, sScale[c + 0], sShift[c + 0]);
                hv.y = fmaf(zv.y, sScale[c + 1], sShift[c + 1]);
                hv.z = fmaf(zv.z, sScale[c + 2], sShift[c + 2]);
                hv.w = fmaf(zv.w, sScale[c + 3], sShift[c + 3]);
                ((float4*)zn_out)[gr * (D / 4) + c4] = hv;
            }
            h4[f] = hv;
        }
    }
    __syncthreads();

    // Stage 2: p = prelu(zn @ Wp + bp)
    {
        int ty = tid >> 5, tx = tid & 31;
        float acc[4][4];
#pragma unroll
        for (int i = 0; i < 4; i++)
#pragma unroll
            for (int j = 0; j < 4; j++) acc[i][j] = 0.f;

#pragma unroll 4
        for (int k = 0; k < D; k++) {
            float hv[4], wv[4];
#pragma unroll
            for (int i = 0; i < 4; i++) hv[i] = sH[(ty + 8 * i) * D + k];
#pragma unroll
            for (int j = 0; j < 4; j++) wv[j] = sW[k * D + tx + 32 * j];
#pragma unroll
            for (int i = 0; i < 4; i++)
#pragma unroll
                for (int j = 0; j < 4; j++) acc[i][j] = fmaf(hv[i], wv[j], acc[i][j]);
        }
        float a = __ldg(&prelu_a[0]);
#pragma unroll
        for (int j = 0; j < 4; j++) {
            float bv = __ldg(&bp[tx + 32 * j]);
#pragma unroll
            for (int i = 0; i < 4; i++) {
                int gr = row0 + ty + 8 * i;
                if (gr < N_NODES) {
                    float v = acc[i][j] + bv;
                    p_out[gr * D + tx + 32 * j] = (v >= 0.f) ? v : a * v;
                }
            }
        }
    }
}

// ---------------------------------------------------------------------------
extern "C" void kernel_launch(void* const* d_in, const int* in_sizes, int n_in,
                              void* d_out, int out_size) {
    const float* x       = (const float*)d_in[0];
    const float* ew      = (const float*)d_in[1];
    const float* W1s     = (const float*)d_in[2];
    const float* b1s     = (const float*)d_in[3];
    const float* W2s     = (const float*)d_in[4];
    const float* b2s     = (const float*)d_in[5];
    const float* eps     = (const float*)d_in[6];
    const float* gamma   = (const float*)d_in[7];
    const float* beta    = (const float*)d_in[8];
    const float* Wp      = (const float*)d_in[9];
    const float* bp      = (const float*)d_in[10];
    const float* prelu_a = (const float*)d_in[11];
    const int*   ei32    = (const int*)d_in[12];   // int32 or int64 (probed)
    float* out = (float*)d_out;

    // Unconditional (no static guards per harness rules); idempotent and cheap.
    cudaFuncSetAttribute(mlp_kernel, cudaFuncAttributeMaxDynamicSharedMemorySize, 98304);
    cudaFuncSetAttribute(proj_kernel, cudaFuncAttributeMaxDynamicSharedMemorySize, 82944);

    const int zeroBlocks = (N_NODES * D / 4) / 256;         // 6250
    const int edgeBlocks = (N_EDGES * 32) / 256;            // 100000
    const int mlpBlocks  = (N_NODES + TILE_R - 1) / TILE_R; // 1563

    probe_idx_kernel<<<1, 1>>>(ei32);
    for (int l = 0; l < 3; l++) {
        zero_agg_kernel<<<zeroBlocks, 256>>>();
        edge_kernel<<<edgeBlocks, 256>>>(x, ew, ei32, l == 0 ? 1 : 0);
        mlp_kernel<<<mlpBlocks, 256, 98304>>>(x, W1s, b1s, W2s, b2s, eps, l);
    }
    bn_stats_kernel<<<512, 128>>>();
    proj_kernel<<<mlpBlocks, 256, 82944>>>(Wp, bp, gamma, beta, prelu_a, out);
}

// round 7
// speedup vs baseline: 1.2961x; 1.2961x over previous
#include <cuda_runtime.h>

#define N_NODES 50000
#define N_EDGES 800000
#define D 128
#define BN_EPS 1e-5f
#define TILE_R 32     // proj tile
#define MT_R 64       // mlp tile rows

// Persistent scratch (static device allocation — allowed; runtime alloc is not).
__device__ __align__(16) float g_z[N_NODES * D];    // current node features
__device__ __align__(16) float g_agg[N_NODES * D];  // aggregation result
__device__ float g_stats[2 * D];                    // BN col sum / sumsq
__device__ int g_idx64;                             // 1 if edge_index is int64
__device__ int g_deg[N_NODES];                      // degree histogram
__device__ int g_cur[N_NODES];                      // scatter cursors
__device__ int g_rowptr[N_NODES + 1];               // CSR row pointers
__device__ int g_esrc[N_EDGES];                     // CSR: src per slot
__device__ __align__(16) float g_ewt[N_EDGES];      // CSR: weight per slot

// ---------------------------------------------------------------------------
// Probe edge_index dtype: int64 little-endian with values < 2^31 has all-zero
// odd 32-bit words (64 samples => false-positive prob ~0). Deterministic.
// ---------------------------------------------------------------------------
__global__ void probe_idx_kernel(const int* __restrict__ ei32) {
    int all_zero = 1;
#pragma unroll
    for (int i = 0; i < 64; i++)
        if (__ldg(&ei32[2 * i + 1]) != 0) all_zero = 0;
    g_idx64 = all_zero;
}

__device__ __forceinline__ int load_src(const int* ei32, int e) {
    int s = g_idx64 ? __ldg(&ei32[2 * e]) : __ldg(&ei32[e]);
    return min(max(s, 0), N_NODES - 1);
}
__device__ __forceinline__ int load_dst(const int* ei32, int e) {
    int d = g_idx64 ? __ldg(&ei32[2 * N_EDGES + 2 * e]) : __ldg(&ei32[N_EDGES + e]);
    return min(max(d, 0), N_NODES - 1);
}

// ---------------------------------------------------------------------------
// CSR build: zero counters -> histogram -> exclusive scan -> scatter
// ---------------------------------------------------------------------------
__global__ void zero_counters_kernel() {
    int i = blockIdx.x * blockDim.x + threadIdx.x;
    if (i < N_NODES) { g_deg[i] = 0; g_cur[i] = 0; }
    if (i < 2 * D) g_stats[i] = 0.f;
}

__global__ void hist_kernel(const int* __restrict__ ei32) {
    int e = blockIdx.x * blockDim.x + threadIdx.x;
    if (e >= N_EDGES) return;
    atomicAdd(&g_deg[load_dst(ei32, e)], 1);
}

// Single-block exclusive scan over g_deg -> g_rowptr (50001 entries).
__global__ void scan_kernel() {
    __shared__ int warp_s[32];
    __shared__ int s_total;
    int tid = threadIdx.x, lane = tid & 31, wid = tid >> 5;
    int carry = 0;
    for (int base = 0; base < N_NODES; base += 1024) {
        int i = base + tid;
        int v = (i < N_NODES) ? g_deg[i] : 0;
        int x = v;
#pragma unroll
        for (int o = 1; o < 32; o <<= 1) {
            int y = __shfl_up_sync(0xFFFFFFFFu, x, o);
            if (lane >= o) x += y;
        }
        if (lane == 31) warp_s[wid] = x;
        __syncthreads();
        if (wid == 0) {
            int w = warp_s[lane];
#pragma unroll
            for (int o = 1; o < 32; o <<= 1) {
                int y = __shfl_up_sync(0xFFFFFFFFu, w, o);
                if (lane >= o) w += y;
            }
            warp_s[lane] = w;
            if (lane == 31) s_total = w;
        }
        __syncthreads();
        int pre = (wid > 0) ? warp_s[wid - 1] : 0;
        if (i < N_NODES) g_rowptr[i] = carry + pre + x - v;
        carry += s_total;
        __syncthreads();
    }
    if (tid == 0) g_rowptr[N_NODES] = carry;
}

__global__ void scatter_kernel(const float* __restrict__ ew,
                               const int* __restrict__ ei32) {
    int e = blockIdx.x * blockDim.x + threadIdx.x;
    if (e >= N_EDGES) return;
    int src = load_src(ei32, e);
    int dst = load_dst(ei32, e);
    int pos = g_rowptr[dst] + atomicAdd(&g_cur[dst], 1);
    g_esrc[pos] = src;
    g_ewt[pos] = __ldg(&ew[e]);
}

// ---------------------------------------------------------------------------
// CSR aggregation: one warp per node. Register accumulation, no atomics,
// no pre-zeroing. Gathers stay L2-resident; one coalesced 512B store/node.
// ---------------------------------------------------------------------------
__global__ void agg_kernel(const float* __restrict__ xin, int use_x) {
    int node = (blockIdx.x * blockDim.x + threadIdx.x) >> 5;
    if (node >= N_NODES) return;
    int lane = threadIdx.x & 31;
    const float* z = use_x ? xin : g_z;

    int beg = __ldg(&g_rowptr[node]);
    int end = __ldg(&g_rowptr[node + 1]);
    float4 acc = make_float4(0.f, 0.f, 0.f, 0.f);
    for (int e = beg; e < end; e++) {
        int src = __ldg(&g_esrc[e]);         // broadcast across warp
        float w = __ldg(&g_ewt[e]);
        float4 v = ((const float4*)(z + (size_t)src * D))[lane];
        acc.x = fmaf(v.x, w, acc.x);
        acc.y = fmaf(v.y, w, acc.y);
        acc.z = fmaf(v.z, w, acc.z);
        acc.w = fmaf(v.w, w, acc.w);
    }
    ((float4*)(g_agg + (size_t)node * D))[lane] = acc;
}

// ---------------------------------------------------------------------------
// Fused GIN node update + 2-layer MLP, crossbar-optimized:
// 64-row tile, 256 threads, 8x4 outputs/thread, W transposed in smem
// (stride 132: conflict-free LDS.128), h rows broadcast. smem = 100352 B.
// ---------------------------------------------------------------------------
#define WT_STRIDE 132

__global__ void mlp_kernel(const float* __restrict__ xin,
                           const float* __restrict__ W1s,
                           const float* __restrict__ b1s,
                           const float* __restrict__ W2s,
                           const float* __restrict__ b2s,
                           const float* __restrict__ epsp,
                           int layer) {
    extern __shared__ float sm[];
    float* sWT = sm;                    // 128*132 = 16896 floats
    float* sH  = sm + 16896;            // 64*128  =  8192 floats

    const float* zin = (layer == 0) ? xin : g_z;
    const float* W1 = W1s + layer * D * D;
    const float* W2 = W2s + layer * D * D;
    const float* b1 = b1s + layer * D;
    const float* b2 = b2s + layer * D;
    const float onePlusEps = 1.f + __ldg(&epsp[layer]);

    int tid = threadIdx.x;
    int ty = tid >> 5;    // warp id 0..7 -> base row
    int tx = tid & 31;    // lane -> base col
    int row0 = blockIdx.x * MT_R;

    // Stage 1: h tile -> sH ; W1^T -> sWT
    {
        const float4* z4 = (const float4*)zin;
        const float4* a4 = (const float4*)g_agg;
        float4* h4 = (float4*)sH;
#pragma unroll
        for (int t = 0; t < 8; t++) {
            int f = tid + t * 256;      // 0..2047
            int r = f >> 5;
            int c4 = f & 31;
            int gr = row0 + r;
            float4 hv = make_float4(0.f, 0.f, 0.f, 0.f);
            if (gr < N_NODES) {
                float4 zv = z4[(size_t)gr * (D / 4) + c4];
                float4 av = a4[(size_t)gr * (D / 4) + c4];
                hv.x = fmaf(onePlusEps, zv.x, av.x);
                hv.y = fmaf(onePlusEps, zv.y, av.y);
                hv.z = fmaf(onePlusEps, zv.z, av.z);
                hv.w = fmaf(onePlusEps, zv.w, av.w);
            }
            h4[f] = hv;
        }
#pragma unroll
        for (int t = 0; t < 64; t++) {
            int idx = tid + t * 256;    // 0..16383
            int k = idx >> 7, n = idx & 127;
            sWT[n * WT_STRIDE + k] = __ldg(&W1[idx]);
        }
    }
    __syncthreads();

    // Stage 2: T = relu(h @ W1 + b1)
    float acc[8][4];
#pragma unroll
    for (int i = 0; i < 8; i++)
#pragma unroll
        for (int j = 0; j < 4; j++) acc[i][j] = 0.f;

#pragma unroll 8
    for (int k4 = 0; k4 < D / 4; k4++) {
        float4 wv[4];
#pragma unroll
        for (int j = 0; j < 4; j++)
            wv[j] = *(const float4*)&sWT[(tx + 32 * j) * WT_STRIDE + k4 * 4];
#pragma unroll
        for (int i = 0; i < 8; i++) {
            float4 hv = *(const float4*)&sH[(ty + 8 * i) * D + k4 * 4];
#pragma unroll
            for (int j = 0; j < 4; j++) {
                acc[i][j] = fmaf(hv.x, wv[j].x, acc[i][j]);
                acc[i][j] = fmaf(hv.y, wv[j].y, acc[i][j]);
                acc[i][j] = fmaf(hv.z, wv[j].z, acc[i][j]);
                acc[i][j] = fmaf(hv.w, wv[j].w, acc[i][j]);
            }
        }
    }
    __syncthreads();   // done reading sH/sWT

    // Write T over sH; load W2^T over sWT
    {
        float bj[4];
#pragma unroll
        for (int j = 0; j < 4; j++) bj[j] = __ldg(&b1[tx + 32 * j]);
#pragma unroll
        for (int i = 0; i < 8; i++)
#pragma unroll
            for (int j = 0; j < 4; j++)
                sH[(ty + 8 * i) * D + tx + 32 * j] = fmaxf(acc[i][j] + bj[j], 0.f);
#pragma unroll
        for (int t = 0; t < 64; t++) {
            int idx = tid + t * 256;
            int k = idx >> 7, n = idx & 127;
            sWT[n * WT_STRIDE + k] = __ldg(&W2[idx]);
        }
    }
    __syncthreads();

    // Stage 3: z_new = relu(T @ W2 + b2) -> g_z
#pragma unroll
    for (int i = 0; i < 8; i++)
#pragma unroll
        for (int j = 0; j < 4; j++) acc[i][j] = 0.f;

#pragma unroll 8
    for (int k4 = 0; k4 < D / 4; k4++) {
        float4 wv[4];
#pragma unroll
        for (int j = 0; j < 4; j++)
            wv[j] = *(const float4*)&sWT[(tx + 32 * j) * WT_STRIDE + k4 * 4];
#pragma unroll
        for (int i = 0; i < 8; i++) {
            float4 hv = *(const float4*)&sH[(ty + 8 * i) * D + k4 * 4];
#pragma unroll
            for (int j = 0; j < 4; j++) {
                acc[i][j] = fmaf(hv.x, wv[j].x, acc[i][j]);
                acc[i][j] = fmaf(hv.y, wv[j].y, acc[i][j]);
                acc[i][j] = fmaf(hv.z, wv[j].z, acc[i][j]);
                acc[i][j] = fmaf(hv.w, wv[j].w, acc[i][j]);
            }
        }
    }
    {
        float bj[4];
#pragma unroll
        for (int j = 0; j < 4; j++) bj[j] = __ldg(&b2[tx + 32 * j]);
#pragma unroll
        for (int i = 0; i < 8; i++) {
            int gr = row0 + ty + 8 * i;
            if (gr < N_NODES) {
#pragma unroll
                for (int j = 0; j < 4; j++)
                    g_z[(size_t)gr * D + tx + 32 * j] = fmaxf(acc[i][j] + bj[j], 0.f);
            }
        }
    }
}

// ---------------------------------------------------------------------------
// BN statistics: per-column sum and sum-of-squares over all nodes.
// ---------------------------------------------------------------------------
__global__ void bn_stats_kernel() {
    int c = threadIdx.x;
    float s = 0.f, ss = 0.f;
    for (int r = blockIdx.x; r < N_NODES; r += gridDim.x) {
        float v = g_z[(size_t)r * D + c];
        s += v;
        ss += v * v;
    }
    atomicAdd(&g_stats[c], s);
    atomicAdd(&g_stats[D + c], ss);
}

// ---------------------------------------------------------------------------
// Fused BN-normalize (writes zn) + projection GEMM + PReLU (writes p).
// ---------------------------------------------------------------------------
__global__ void proj_kernel(const float* __restrict__ Wp,
                            const float* __restrict__ bp,
                            const float* __restrict__ gamma,
                            const float* __restrict__ beta,
                            const float* __restrict__ prelu_a,
                            float* __restrict__ out) {
    extern __shared__ float sm[];
    float* sW = sm;              // 16384
    float* sH = sm + 16384;      // 4096
    float* sScale = sm + 20480;  // 128
    float* sShift = sm + 20608;  // 128

    int tid = threadIdx.x;
    if (tid < D) {
        float mean = g_stats[tid] * (1.f / N_NODES);
        float var = g_stats[D + tid] * (1.f / N_NODES) - mean * mean;
        float rs = rsqrtf(var + BN_EPS);
        float sc = __ldg(&gamma[tid]) * rs;
        sScale[tid] = sc;
        sShift[tid] = __ldg(&beta[tid]) - mean * sc;
    }
    {
        const float4* w4 = (const float4*)Wp;
        float4* s4 = (float4*)sW;
#pragma unroll
        for (int t = 0; t < 16; t++) s4[tid + t * 256] = w4[tid + t * 256];
    }
    __syncthreads();

    int row0 = blockIdx.x * TILE_R;
    float* zn_out = out;
    float* p_out = out + (size_t)N_NODES * D;

    {
        const float4* z4 = (const float4*)g_z;
        float4* h4 = (float4*)sH;
#pragma unroll
        for (int t = 0; t < 4; t++) {
            int f = tid + t * 256;
            int r = f >> 5;
            int c4 = f & 31;
            int gr = row0 + r;
            float4 hv = make_float4(0.f, 0.f, 0.f, 0.f);
            if (gr < N_NODES) {
                float4 zv = z4[(size_t)gr * (D / 4) + c4];
                int c = c4 * 4;
                hv.x = fmaf(zv.x, sScale[c + 0], sShift[c + 0]);
                hv.y = fmaf(zv.y, sScale[c + 1], sShift[c + 1]);
                hv.z = fmaf(zv.z, sScale[c + 2], sShift[c + 2]);
                hv.w = fmaf(zv.w, sScale[c + 3], sShift[c + 3]);
                ((float4*)zn_out)[(size_t)gr * (D / 4) + c4] = hv;
            }
            h4[f] = hv;
        }
    }
    __syncthreads();

    {
        int ty = tid >> 5, tx = tid & 31;
        float acc[4][4];
#pragma unroll
        for (int i = 0; i < 4; i++)
#pragma unroll
            for (int j = 0; j < 4; j++) acc[i][j] = 0.f;

#pragma unroll 4
        for (int k = 0; k < D; k++) {
            float hv[4], wv[4];
#pragma unroll
            for (int i = 0; i < 4; i++) hv[i] = sH[(ty + 8 * i) * D + k];
#pragma unroll
            for (int j = 0; j < 4; j++) wv[j] = sW[k * D + tx + 32 * j];
#pragma unroll
            for (int i = 0; i < 4; i++)
#pragma unroll
                for (int j = 0; j < 4; j++) acc[i][j] = fmaf(hv[i], wv[j], acc[i][j]);
        }
        float a = __ldg(&prelu_a[0]);
#pragma unroll
        for (int j = 0; j < 4; j++) {
            float bv = __ldg(&bp[tx + 32 * j]);
#pragma unroll
            for (int i = 0; i < 4; i++) {
                int gr = row0 + ty + 8 * i;
                if (gr < N_NODES) {
                    float v = acc[i][j] + bv;
                    p_out[(size_t)gr * D + tx + 32 * j] = (v >= 0.f) ? v : a * v;
                }
            }
        }
    }
}

// ---------------------------------------------------------------------------
extern "C" void kernel_launch(void* const* d_in, const int* in_sizes, int n_in,
                              void* d_out, int out_size) {
    const float* x       = (const float*)d_in[0];
    const float* ew      = (const float*)d_in[1];
    const float* W1s     = (const float*)d_in[2];
    const float* b1s     = (const float*)d_in[3];
    const float* W2s     = (const float*)d_in[4];
    const float* b2s     = (const float*)d_in[5];
    const float* eps     = (const float*)d_in[6];
    const float* gamma   = (const float*)d_in[7];
    const float* beta    = (const float*)d_in[8];
    const float* Wp      = (const float*)d_in[9];
    const float* bp      = (const float*)d_in[10];
    const float* prelu_a = (const float*)d_in[11];
    const int*   ei32    = (const int*)d_in[12];
    float* out = (float*)d_out;

    cudaFuncSetAttribute(mlp_kernel, cudaFuncAttributeMaxDynamicSharedMemorySize, 100352);
    cudaFuncSetAttribute(proj_kernel, cudaFuncAttributeMaxDynamicSharedMemorySize, 82944);

    const int edgeBlocks = (N_EDGES + 255) / 256;           // 3125
    const int mlpBlocks  = (N_NODES + MT_R - 1) / MT_R;     // 782
    const int aggBlocks  = (N_NODES * 32 + 255) / 256;      // 6250
    const int projBlocks = (N_NODES + TILE_R - 1) / TILE_R; // 1563

    // Build CSR once per call (reused by all 3 layers)
    probe_idx_kernel<<<1, 1>>>(ei32);
    zero_counters_kernel<<<(N_NODES + 255) / 256, 256>>>();
    hist_kernel<<<edgeBlocks, 256>>>(ei32);
    scan_kernel<<<1, 1024>>>();
    scatter_kernel<<<edgeBlocks, 256>>>(ew, ei32);

    for (int l = 0; l < 3; l++) {
        agg_kernel<<<aggBlocks, 256>>>(x, l == 0 ? 1 : 0);
        mlp_kernel<<<mlpBlocks, 256, 100352>>>(x, W1s, b1s, W2s, b2s, eps, l);
    }
    bn_stats_kernel<<<512, 128>>>();
    proj_kernel<<<projBlocks, 256, 82944>>>(Wp, bp, gamma, beta, prelu_a, out);
}

// round 8
// speedup vs baseline: 1.3368x; 1.0314x over previous
#include <cuda_runtime.h>

#define N_NODES 50000
#define N_EDGES 800000
#define D 128
#define BN_EPS 1e-5f
#define TILE_R 32     // proj tile
#define MT_R 64       // mlp tile rows
#define SCAN_CHUNK 512
#define N_CHUNKS ((N_NODES + SCAN_CHUNK - 1) / SCAN_CHUNK)   // 98

// Persistent scratch (static device allocation — allowed; runtime alloc is not).
__device__ __align__(16) float g_z[N_NODES * D];    // current node features
__device__ __align__(16) float g_agg[N_NODES * D];  // aggregation result
__device__ float g_stats[2 * D];                    // BN col sum / sumsq
__device__ int g_idx64;                             // 1 if edge_index is int64
__device__ int g_deg[N_NODES];                      // degree histogram
__device__ int g_cur[N_NODES];                      // scatter cursors (=rowptr)
__device__ int g_rowptr[N_NODES + 1];               // CSR row pointers
__device__ int g_part[N_CHUNKS];                    // chunk totals for scan
__device__ int g_esrc[N_EDGES];                     // CSR: src per slot
__device__ __align__(16) float g_ewt[N_EDGES];      // CSR: weight per slot

// ---------------------------------------------------------------------------
// Probe edge_index dtype: int64 little-endian with values < 2^31 has all-zero
// odd 32-bit words (64 samples => false-positive prob ~0). Deterministic.
// ---------------------------------------------------------------------------
__global__ void probe_idx_kernel(const int* __restrict__ ei32) {
    int all_zero = 1;
#pragma unroll
    for (int i = 0; i < 64; i++)
        if (__ldg(&ei32[2 * i + 1]) != 0) all_zero = 0;
    g_idx64 = all_zero;
}

__device__ __forceinline__ int load_src(const int* ei32, int e) {
    int s = g_idx64 ? __ldg(&ei32[2 * e]) : __ldg(&ei32[e]);
    return min(max(s, 0), N_NODES - 1);
}
__device__ __forceinline__ int load_dst(const int* ei32, int e) {
    int d = g_idx64 ? __ldg(&ei32[2 * N_EDGES + 2 * e]) : __ldg(&ei32[N_EDGES + e]);
    return min(max(d, 0), N_NODES - 1);
}

// ---------------------------------------------------------------------------
// CSR build: zero -> histogram -> 3-phase parallel scan -> scatter
// ---------------------------------------------------------------------------
__global__ void zero_counters_kernel() {
    int i = blockIdx.x * blockDim.x + threadIdx.x;
    if (i < N_NODES) g_deg[i] = 0;
    if (i < 2 * D) g_stats[i] = 0.f;
}

__global__ void hist_kernel(const int* __restrict__ ei32) {
    int e = blockIdx.x * blockDim.x + threadIdx.x;
    if (e >= N_EDGES) return;
    atomicAdd(&g_deg[load_dst(ei32, e)], 1);
}

// Phase 1: per-chunk exclusive scan (chunk = 512) + chunk total.
__global__ void scan_partial_kernel() {
    __shared__ int wsum[16];
    int tid = threadIdx.x, lane = tid & 31, wid = tid >> 5;
    int i = blockIdx.x * SCAN_CHUNK + tid;
    int v = (i < N_NODES) ? g_deg[i] : 0;
    int x = v;
#pragma unroll
    for (int o = 1; o < 32; o <<= 1) {
        int y = __shfl_up_sync(0xFFFFFFFFu, x, o);
        if (lane >= o) x += y;
    }
    if (lane == 31) wsum[wid] = x;
    __syncthreads();
    if (wid == 0 && lane < 16) {
        int w = wsum[lane];
#pragma unroll
        for (int o = 1; o < 16; o <<= 1) {
            int y = __shfl_up_sync(0x0000FFFFu, w, o);
            if (lane >= o) w += y;
        }
        wsum[lane] = w;
    }
    __syncthreads();
    int base = (wid > 0) ? wsum[wid - 1] : 0;
    if (i < N_NODES) g_rowptr[i] = base + x - v;   // chunk-local exclusive
    if (tid == SCAN_CHUNK - 1) g_part[blockIdx.x] = base + x;  // chunk total
}

// Phase 2: single small block scans the 98 chunk totals (exclusive) + total.
__global__ void scan_part_kernel() {
    __shared__ int wsum[4];
    int tid = threadIdx.x, lane = tid & 31, wid = tid >> 5;   // 128 threads
    int v = (tid < N_CHUNKS) ? g_part[tid] : 0;
    int x = v;
#pragma unroll
    for (int o = 1; o < 32; o <<= 1) {
        int y = __shfl_up_sync(0xFFFFFFFFu, x, o);
        if (lane >= o) x += y;
    }
    if (lane == 31) wsum[wid] = x;
    __syncthreads();
    int base = 0;
    for (int w = 0; w < wid; w++) base += wsum[w];
    __syncthreads();
    if (tid < N_CHUNKS) g_part[tid] = base + x - v;           // exclusive
    if (tid == N_CHUNKS - 1) g_rowptr[N_NODES] = base + x;    // grand total
}

// Phase 3: add chunk offsets; init scatter cursors to rowptr.
__global__ void scan_add_kernel() {
    int i = blockIdx.x * blockDim.x + threadIdx.x;
    if (i >= N_NODES) return;
    int r = g_rowptr[i] + g_part[i >> 9];
    g_rowptr[i] = r;
    g_cur[i] = r;
}

__global__ void scatter_kernel(const float* __restrict__ ew,
                               const int* __restrict__ ei32) {
    int e = blockIdx.x * blockDim.x + threadIdx.x;
    if (e >= N_EDGES) return;
    int src = load_src(ei32, e);
    int dst = load_dst(ei32, e);
    int pos = atomicAdd(&g_cur[dst], 1);
    g_esrc[pos] = src;
    g_ewt[pos] = __ldg(&ew[e]);
}

// ---------------------------------------------------------------------------
// CSR aggregation: one warp per node, register accumulation, no atomics.
// 2-edge unroll keeps two 512B gathers in flight per warp.
// ---------------------------------------------------------------------------
__global__ void agg_kernel(const float* __restrict__ xin, int use_x) {
    int node = (blockIdx.x * blockDim.x + threadIdx.x) >> 5;
    if (node >= N_NODES) return;
    int lane = threadIdx.x & 31;
    const float* z = use_x ? xin : g_z;

    int beg = __ldg(&g_rowptr[node]);
    int end = __ldg(&g_rowptr[node + 1]);
    float4 acc = make_float4(0.f, 0.f, 0.f, 0.f);
    int e = beg;
    for (; e + 2 <= end; e += 2) {
        int s0 = __ldg(&g_esrc[e]);
        int s1 = __ldg(&g_esrc[e + 1]);
        float w0 = __ldg(&g_ewt[e]);
        float w1 = __ldg(&g_ewt[e + 1]);
        float4 v0 = ((const float4*)(z + (size_t)s0 * D))[lane];
        float4 v1 = ((const float4*)(z + (size_t)s1 * D))[lane];
        acc.x = fmaf(v0.x, w0, acc.x); acc.y = fmaf(v0.y, w0, acc.y);
        acc.z = fmaf(v0.z, w0, acc.z); acc.w = fmaf(v0.w, w0, acc.w);
        acc.x = fmaf(v1.x, w1, acc.x); acc.y = fmaf(v1.y, w1, acc.y);
        acc.z = fmaf(v1.z, w1, acc.z); acc.w = fmaf(v1.w, w1, acc.w);
    }
    if (e < end) {
        int s0 = __ldg(&g_esrc[e]);
        float w0 = __ldg(&g_ewt[e]);
        float4 v0 = ((const float4*)(z + (size_t)s0 * D))[lane];
        acc.x = fmaf(v0.x, w0, acc.x); acc.y = fmaf(v0.y, w0, acc.y);
        acc.z = fmaf(v0.z, w0, acc.z); acc.w = fmaf(v0.w, w0, acc.w);
    }
    ((float4*)(g_agg + (size_t)node * D))[lane] = acc;
}

// ---------------------------------------------------------------------------
// Fused GIN node update + 2-layer MLP, crossbar-optimized:
// 64-row tile, 256 threads, 8x4 outputs/thread, W transposed in smem
// (stride 132: conflict-free LDS.128), h rows broadcast. smem = 100352 B.
// ---------------------------------------------------------------------------
#define WT_STRIDE 132

__global__ void mlp_kernel(const float* __restrict__ xin,
                           const float* __restrict__ W1s,
                           const float* __restrict__ b1s,
                           const float* __restrict__ W2s,
                           const float* __restrict__ b2s,
                           const float* __restrict__ epsp,
                           int layer) {
    extern __shared__ float sm[];
    float* sWT = sm;                    // 128*132 = 16896 floats
    float* sH  = sm + 16896;            // 64*128  =  8192 floats

    const float* zin = (layer == 0) ? xin : g_z;
    const float* W1 = W1s + layer * D * D;
    const float* W2 = W2s + layer * D * D;
    const float* b1 = b1s + layer * D;
    const float* b2 = b2s + layer * D;
    const float onePlusEps = 1.f + __ldg(&epsp[layer]);

    int tid = threadIdx.x;
    int ty = tid >> 5;    // warp id 0..7 -> base row
    int tx = tid & 31;    // lane -> base col
    int row0 = blockIdx.x * MT_R;

    // Stage 1: h tile -> sH ; W1^T -> sWT
    {
        const float4* z4 = (const float4*)zin;
        const float4* a4 = (const float4*)g_agg;
        float4* h4 = (float4*)sH;
#pragma unroll
        for (int t = 0; t < 8; t++) {
            int f = tid + t * 256;      // 0..2047
            int r = f >> 5;
            int c4 = f & 31;
            int gr = row0 + r;
            float4 hv = make_float4(0.f, 0.f, 0.f, 0.f);
            if (gr < N_NODES) {
                float4 zv = z4[(size_t)gr * (D / 4) + c4];
                float4 av = a4[(size_t)gr * (D / 4) + c4];
                hv.x = fmaf(onePlusEps, zv.x, av.x);
                hv.y = fmaf(onePlusEps, zv.y, av.y);
                hv.z = fmaf(onePlusEps, zv.z, av.z);
                hv.w = fmaf(onePlusEps, zv.w, av.w);
            }
            h4[f] = hv;
        }
#pragma unroll
        for (int t = 0; t < 64; t++) {
            int idx = tid + t * 256;    // 0..16383
            int k = idx >> 7, n = idx & 127;
            sWT[n * WT_STRIDE + k] = __ldg(&W1[idx]);
        }
    }
    __syncthreads();

    // Stage 2: T = relu(h @ W1 + b1)
    float acc[8][4];
#pragma unroll
    for (int i = 0; i < 8; i++)
#pragma unroll
        for (int j = 0; j < 4; j++) acc[i][j] = 0.f;

#pragma unroll 8
    for (int k4 = 0; k4 < D / 4; k4++) {
        float4 wv[4];
#pragma unroll
        for (int j = 0; j < 4; j++)
            wv[j] = *(const float4*)&sWT[(tx + 32 * j) * WT_STRIDE + k4 * 4];
#pragma unroll
        for (int i = 0; i < 8; i++) {
            float4 hv = *(const float4*)&sH[(ty + 8 * i) * D + k4 * 4];
#pragma unroll
            for (int j = 0; j < 4; j++) {
                acc[i][j] = fmaf(hv.x, wv[j].x, acc[i][j]);
                acc[i][j] = fmaf(hv.y, wv[j].y, acc[i][j]);
                acc[i][j] = fmaf(hv.z, wv[j].z, acc[i][j]);
                acc[i][j] = fmaf(hv.w, wv[j].w, acc[i][j]);
            }
        }
    }
    __syncthreads();   // done reading sH/sWT

    // Write T over sH; load W2^T over sWT
    {
        float bj[4];
#pragma unroll
        for (int j = 0; j < 4; j++) bj[j] = __ldg(&b1[tx + 32 * j]);
#pragma unroll
        for (int i = 0; i < 8; i++)
#pragma unroll
            for (int j = 0; j < 4; j++)
                sH[(ty + 8 * i) * D + tx + 32 * j] = fmaxf(acc[i][j] + bj[j], 0.f);
#pragma unroll
        for (int t = 0; t < 64; t++) {
            int idx = tid + t * 256;
            int k = idx >> 7, n = idx & 127;
            sWT[n * WT_STRIDE + k] = __ldg(&W2[idx]);
        }
    }
    __syncthreads();

    // Stage 3: z_new = relu(T @ W2 + b2) -> g_z
#pragma unroll
    for (int i = 0; i < 8; i++)
#pragma unroll
        for (int j = 0; j < 4; j++) acc[i][j] = 0.f;

#pragma unroll 8
    for (int k4 = 0; k4 < D / 4; k4++) {
        float4 wv[4];
#pragma unroll
        for (int j = 0; j < 4; j++)
            wv[j] = *(const float4*)&sWT[(tx + 32 * j) * WT_STRIDE + k4 * 4];
#pragma unroll
        for (int i = 0; i < 8; i++) {
            float4 hv = *(const float4*)&sH[(ty + 8 * i) * D + k4 * 4];
#pragma unroll
            for (int j = 0; j < 4; j++) {
                acc[i][j] = fmaf(hv.x, wv[j].x, acc[i][j]);
                acc[i][j] = fmaf(hv.y, wv[j].y, acc[i][j]);
                acc[i][j] = fmaf(hv.z, wv[j].z, acc[i][j]);
                acc[i][j] = fmaf(hv.w, wv[j].w, acc[i][j]);
            }
        }
    }
    {
        float bj[4];
#pragma unroll
        for (int j = 0; j < 4; j++) bj[j] = __ldg(&b2[tx + 32 * j]);
#pragma unroll
        for (int i = 0; i < 8; i++) {
            int gr = row0 + ty + 8 * i;
            if (gr < N_NODES) {
#pragma unroll
                for (int j = 0; j < 4; j++)
                    g_z[(size_t)gr * D + tx + 32 * j] = fmaxf(acc[i][j] + bj[j], 0.f);
            }
        }
    }
}

// ---------------------------------------------------------------------------
// BN statistics: per-column sum and sum-of-squares over all nodes.
// ---------------------------------------------------------------------------
__global__ void bn_stats_kernel() {
    int c = threadIdx.x;
    float s = 0.f, ss = 0.f;
    for (int r = blockIdx.x; r < N_NODES; r += gridDim.x) {
        float v = g_z[(size_t)r * D + c];
        s += v;
        ss += v * v;
    }
    atomicAdd(&g_stats[c], s);
    atomicAdd(&g_stats[D + c], ss);
}

// ---------------------------------------------------------------------------
// Fused BN-normalize (writes zn) + projection GEMM + PReLU (writes p).
// ---------------------------------------------------------------------------
__global__ void proj_kernel(const float* __restrict__ Wp,
                            const float* __restrict__ bp,
                            const float* __restrict__ gamma,
                            const float* __restrict__ beta,
                            const float* __restrict__ prelu_a,
                            float* __restrict__ out) {
    extern __shared__ float sm[];
    float* sW = sm;              // 16384
    float* sH = sm + 16384;      // 4096
    float* sScale = sm + 20480;  // 128
    float* sShift = sm + 20608;  // 128

    int tid = threadIdx.x;
    if (tid < D) {
        float mean = g_stats[tid] * (1.f / N_NODES);
        float var = g_stats[D + tid] * (1.f / N_NODES) - mean * mean;
        float rs = rsqrtf(var + BN_EPS);
        float sc = __ldg(&gamma[tid]) * rs;
        sScale[tid] = sc;
        sShift[tid] = __ldg(&beta[tid]) - mean * sc;
    }
    {
        const float4* w4 = (const float4*)Wp;
        float4* s4 = (float4*)sW;
#pragma unroll
        for (int t = 0; t < 16; t++) s4[tid + t * 256] = w4[tid + t * 256];
    }
    __syncthreads();

    int row0 = blockIdx.x * TILE_R;
    float* zn_out = out;
    float* p_out = out + (size_t)N_NODES * D;

    {
        const float4* z4 = (const float4*)g_z;
        float4* h4 = (float4*)sH;
#pragma unroll
        for (int t = 0; t < 4; t++) {
            int f = tid + t * 256;
            int r = f >> 5;
            int c4 = f & 31;
            int gr = row0 + r;
            float4 hv = make_float4(0.f, 0.f, 0.f, 0.f);
            if (gr < N_NODES) {
                float4 zv = z4[(size_t)gr * (D / 4) + c4];
                int c = c4 * 4;
                hv.x = fmaf(zv.x, sScale[c + 0], sShift[c + 0]);
                hv.y = fmaf(zv.y, sScale[c + 1], sShift[c + 1]);
                hv.z = fmaf(zv.z, sScale[c + 2], sShift[c + 2]);
                hv.w = fmaf(zv.w, sScale[c + 3], sShift[c + 3]);
                ((float4*)zn_out)[(size_t)gr * (D / 4) + c4] = hv;
            }
            h4[f] = hv;
        }
    }
    __syncthreads();

    {
        int ty = tid >> 5, tx = tid & 31;
        float acc[4][4];
#pragma unroll
        for (int i = 0; i < 4; i++)
#pragma unroll
            for (int j = 0; j < 4; j++) acc[i][j] = 0.f;

#pragma unroll 4
        for (int k = 0; k < D; k++) {
            float hv[4], wv[4];
#pragma unroll
            for (int i = 0; i < 4; i++) hv[i] = sH[(ty + 8 * i) * D + k];
#pragma unroll
            for (int j = 0; j < 4; j++) wv[j] = sW[k * D + tx + 32 * j];
#pragma unroll
            for (int i = 0; i < 4; i++)
#pragma unroll
                for (int j = 0; j < 4; j++) acc[i][j] = fmaf(hv[i], wv[j], acc[i][j]);
        }
        float a = __ldg(&prelu_a[0]);
#pragma unroll
        for (int j = 0; j < 4; j++) {
            float bv = __ldg(&bp[tx + 32 * j]);
#pragma unroll
            for (int i = 0; i < 4; i++) {
                int gr = row0 + ty + 8 * i;
                if (gr < N_NODES) {
                    float v = acc[i][j] + bv;
                    p_out[(size_t)gr * D + tx + 32 * j] = (v >= 0.f) ? v : a * v;
                }
            }
        }
    }
}

// ---------------------------------------------------------------------------
extern "C" void kernel_launch(void* const* d_in, const int* in_sizes, int n_in,
                              void* d_out, int out_size) {
    const float* x       = (const float*)d_in[0];
    const float* ew      = (const float*)d_in[1];
    const float* W1s     = (const float*)d_in[2];
    const float* b1s     = (const float*)d_in[3];
    const float* W2s     = (const float*)d_in[4];
    const float* b2s     = (const float*)d_in[5];
    const float* eps     = (const float*)d_in[6];
    const float* gamma   = (const float*)d_in[7];
    const float* beta    = (const float*)d_in[8];
    const float* Wp      = (const float*)d_in[9];
    const float* bp      = (const float*)d_in[10];
    const float* prelu_a = (const float*)d_in[11];
    const int*   ei32    = (const int*)d_in[12];
    float* out = (float*)d_out;

    cudaFuncSetAttribute(mlp_kernel, cudaFuncAttributeMaxDynamicSharedMemorySize, 100352);
    cudaFuncSetAttribute(proj_kernel, cudaFuncAttributeMaxDynamicSharedMemorySize, 82944);

    const int edgeBlocks = (N_EDGES + 255) / 256;           // 3125
    const int mlpBlocks  = (N_NODES + MT_R - 1) / MT_R;     // 782
    const int aggBlocks  = (N_NODES * 32 + 255) / 256;      // 6250
    const int projBlocks = (N_NODES + TILE_R - 1) / TILE_R; // 1563
    const int nodeBlocks = (N_NODES + 255) / 256;           // 196

    // Build CSR once per call (reused by all 3 layers)
    probe_idx_kernel<<<1, 1>>>(ei32);
    zero_counters_kernel<<<nodeBlocks, 256>>>();
    hist_kernel<<<edgeBlocks, 256>>>(ei32);
    scan_partial_kernel<<<N_CHUNKS, SCAN_CHUNK>>>();
    scan_part_kernel<<<1, 128>>>();
    scan_add_kernel<<<nodeBlocks, 256>>>();
    scatter_kernel<<<edgeBlocks, 256>>>(ew, ei32);

    for (int l = 0; l < 3; l++) {
        agg_kernel<<<aggBlocks, 256>>>(x, l == 0 ? 1 : 0);
        mlp_kernel<<<mlpBlocks, 256, 100352>>>(x, W1s, b1s, W2s, b2s, eps, l);
    }
    bn_stats_kernel<<<512, 128>>>();
    proj_kernel<<<projBlocks, 256, 82944>>>(Wp, bp, gamma, beta, prelu_a, out);
}

// round 9
// speedup vs baseline: 1.4556x; 1.0889x over previous
#include <cuda_runtime.h>

#define N_NODES 50000
#define N_EDGES 800000
#define D 128
#define BN_EPS 1e-5f
#define MT_R 64       // mlp/proj tile rows
#define SCAN_CHUNK 512
#define N_CHUNKS ((N_NODES + SCAN_CHUNK - 1) / SCAN_CHUNK)   // 98
#define WT_STRIDE 132

// Persistent scratch (static device allocation — allowed; runtime alloc is not).
__device__ __align__(16) float g_z[N_NODES * D];    // current node features
__device__ __align__(16) float g_agg[N_NODES * D];  // aggregation result
__device__ float g_stats[2 * D];                    // BN col sum / sumsq
__device__ int g_idx64;                             // 1 if edge_index is int64
__device__ int g_deg[N_NODES];                      // degree histogram
__device__ int g_cur[N_NODES];                      // scatter cursors (=rowptr)
__device__ int g_rowptr[N_NODES + 1];               // CSR row pointers
__device__ int g_part[N_CHUNKS];                    // chunk totals for scan
__device__ int g_esrc[N_EDGES];                     // CSR: src per slot
__device__ __align__(16) float g_ewt[N_EDGES];      // CSR: weight per slot

// ---------------------------------------------------------------------------
// Zero counters + BN stats; block 0 thread 0 also probes edge_index dtype
// (int64 LE with values < 2^31 has all-zero odd 32-bit words; 64 samples).
// ---------------------------------------------------------------------------
__global__ void zero_counters_kernel(const int* __restrict__ ei32) {
    int i = blockIdx.x * blockDim.x + threadIdx.x;
    if (i < N_NODES) g_deg[i] = 0;
    if (i < 2 * D) g_stats[i] = 0.f;
    if (i == 0) {
        int all_zero = 1;
#pragma unroll
        for (int k = 0; k < 64; k++)
            if (__ldg(&ei32[2 * k + 1]) != 0) all_zero = 0;
        g_idx64 = all_zero;
    }
}

__device__ __forceinline__ int load_src(const int* ei32, int e) {
    int s = g_idx64 ? __ldg(&ei32[2 * e]) : __ldg(&ei32[e]);
    return min(max(s, 0), N_NODES - 1);
}
__device__ __forceinline__ int load_dst(const int* ei32, int e) {
    int d = g_idx64 ? __ldg(&ei32[2 * N_EDGES + 2 * e]) : __ldg(&ei32[N_EDGES + e]);
    return min(max(d, 0), N_NODES - 1);
}

__global__ void hist_kernel(const int* __restrict__ ei32) {
    int e = blockIdx.x * blockDim.x + threadIdx.x;
    if (e >= N_EDGES) return;
    atomicAdd(&g_deg[load_dst(ei32, e)], 1);
}

// Phase 1: per-chunk exclusive scan (chunk = 512) + chunk total.
__global__ void scan_partial_kernel() {
    __shared__ int wsum[16];
    int tid = threadIdx.x, lane = tid & 31, wid = tid >> 5;
    int i = blockIdx.x * SCAN_CHUNK + tid;
    int v = (i < N_NODES) ? g_deg[i] : 0;
    int x = v;
#pragma unroll
    for (int o = 1; o < 32; o <<= 1) {
        int y = __shfl_up_sync(0xFFFFFFFFu, x, o);
        if (lane >= o) x += y;
    }
    if (lane == 31) wsum[wid] = x;
    __syncthreads();
    if (wid == 0 && lane < 16) {
        int w = wsum[lane];
#pragma unroll
        for (int o = 1; o < 16; o <<= 1) {
            int y = __shfl_up_sync(0x0000FFFFu, w, o);
            if (lane >= o) w += y;
        }
        wsum[lane] = w;
    }
    __syncthreads();
    int base = (wid > 0) ? wsum[wid - 1] : 0;
    if (i < N_NODES) g_rowptr[i] = base + x - v;
    if (tid == SCAN_CHUNK - 1) g_part[blockIdx.x] = base + x;
}

// Phase 2: single small block scans the 98 chunk totals (exclusive) + total.
__global__ void scan_part_kernel() {
    __shared__ int wsum[4];
    int tid = threadIdx.x, lane = tid & 31, wid = tid >> 5;   // 128 threads
    int v = (tid < N_CHUNKS) ? g_part[tid] : 0;
    int x = v;
#pragma unroll
    for (int o = 1; o < 32; o <<= 1) {
        int y = __shfl_up_sync(0xFFFFFFFFu, x, o);
        if (lane >= o) x += y;
    }
    if (lane == 31) wsum[wid] = x;
    __syncthreads();
    int base = 0;
    for (int w = 0; w < wid; w++) base += wsum[w];
    __syncthreads();
    if (tid < N_CHUNKS) g_part[tid] = base + x - v;
    if (tid == N_CHUNKS - 1) g_rowptr[N_NODES] = base + x;
}

// Phase 3: add chunk offsets; init scatter cursors to rowptr.
__global__ void scan_add_kernel() {
    int i = blockIdx.x * blockDim.x + threadIdx.x;
    if (i >= N_NODES) return;
    int r = g_rowptr[i] + g_part[i >> 9];
    g_rowptr[i] = r;
    g_cur[i] = r;
}

__global__ void scatter_kernel(const float* __restrict__ ew,
                               const int* __restrict__ ei32) {
    int e = blockIdx.x * blockDim.x + threadIdx.x;
    if (e >= N_EDGES) return;
    int src = load_src(ei32, e);
    int dst = load_dst(ei32, e);
    int pos = atomicAdd(&g_cur[dst], 1);
    g_esrc[pos] = src;
    g_ewt[pos] = __ldg(&ew[e]);
}

// ---------------------------------------------------------------------------
// CSR aggregation: one warp per node, register accumulation, no atomics.
// 4-edge unroll keeps four 512B gathers in flight per warp.
// ---------------------------------------------------------------------------
__global__ void agg_kernel(const float* __restrict__ xin, int use_x) {
    int node = (blockIdx.x * blockDim.x + threadIdx.x) >> 5;
    if (node >= N_NODES) return;
    int lane = threadIdx.x & 31;
    const float* z = use_x ? xin : g_z;

    int beg = __ldg(&g_rowptr[node]);
    int end = __ldg(&g_rowptr[node + 1]);
    float4 acc = make_float4(0.f, 0.f, 0.f, 0.f);
    int e = beg;
    for (; e + 4 <= end; e += 4) {
        int s0 = __ldg(&g_esrc[e]);
        int s1 = __ldg(&g_esrc[e + 1]);
        int s2 = __ldg(&g_esrc[e + 2]);
        int s3 = __ldg(&g_esrc[e + 3]);
        float w0 = __ldg(&g_ewt[e]);
        float w1 = __ldg(&g_ewt[e + 1]);
        float w2 = __ldg(&g_ewt[e + 2]);
        float w3 = __ldg(&g_ewt[e + 3]);
        float4 v0 = ((const float4*)(z + (size_t)s0 * D))[lane];
        float4 v1 = ((const float4*)(z + (size_t)s1 * D))[lane];
        float4 v2 = ((const float4*)(z + (size_t)s2 * D))[lane];
        float4 v3 = ((const float4*)(z + (size_t)s3 * D))[lane];
        acc.x = fmaf(v0.x, w0, acc.x); acc.y = fmaf(v0.y, w0, acc.y);
        acc.z = fmaf(v0.z, w0, acc.z); acc.w = fmaf(v0.w, w0, acc.w);
        acc.x = fmaf(v1.x, w1, acc.x); acc.y = fmaf(v1.y, w1, acc.y);
        acc.z = fmaf(v1.z, w1, acc.z); acc.w = fmaf(v1.w, w1, acc.w);
        acc.x = fmaf(v2.x, w2, acc.x); acc.y = fmaf(v2.y, w2, acc.y);
        acc.z = fmaf(v2.z, w2, acc.z); acc.w = fmaf(v2.w, w2, acc.w);
        acc.x = fmaf(v3.x, w3, acc.x); acc.y = fmaf(v3.y, w3, acc.y);
        acc.z = fmaf(v3.z, w3, acc.z); acc.w = fmaf(v3.w, w3, acc.w);
    }
    for (; e < end; e++) {
        int s0 = __ldg(&g_esrc[e]);
        float w0 = __ldg(&g_ewt[e]);
        float4 v0 = ((const float4*)(z + (size_t)s0 * D))[lane];
        acc.x = fmaf(v0.x, w0, acc.x); acc.y = fmaf(v0.y, w0, acc.y);
        acc.z = fmaf(v0.z, w0, acc.z); acc.w = fmaf(v0.w, w0, acc.w);
    }
    ((float4*)(g_agg + (size_t)node * D))[lane] = acc;
}

// ---------------------------------------------------------------------------
// Fused GIN node update + 2-layer MLP, crossbar-optimized. On layer 2, the
// epilogue also accumulates BN column sums/sumsqs (tile-reduce + 2 atomics/col).
// ---------------------------------------------------------------------------
__global__ void mlp_kernel(const float* __restrict__ xin,
                           const float* __restrict__ W1s,
                           const float* __restrict__ b1s,
                           const float* __restrict__ W2s,
                           const float* __restrict__ b2s,
                           const float* __restrict__ epsp,
                           int layer) {
    extern __shared__ float sm[];
    float* sWT = sm;                    // 128*132 = 16896 floats
    float* sH  = sm + 16896;            // 64*128  =  8192 floats

    const float* zin = (layer == 0) ? xin : g_z;
    const float* W1 = W1s + layer * D * D;
    const float* W2 = W2s + layer * D * D;
    const float* b1 = b1s + layer * D;
    const float* b2 = b2s + layer * D;
    const float onePlusEps = 1.f + __ldg(&epsp[layer]);

    int tid = threadIdx.x;
    int ty = tid >> 5;    // warp id 0..7 -> base row
    int tx = tid & 31;    // lane -> base col
    int row0 = blockIdx.x * MT_R;

    // Stage 1: h tile -> sH ; W1^T -> sWT
    {
        const float4* z4 = (const float4*)zin;
        const float4* a4 = (const float4*)g_agg;
        float4* h4 = (float4*)sH;
#pragma unroll
        for (int t = 0; t < 8; t++) {
            int f = tid + t * 256;      // 0..2047
            int r = f >> 5;
            int c4 = f & 31;
            int gr = row0 + r;
            float4 hv = make_float4(0.f, 0.f, 0.f, 0.f);
            if (gr < N_NODES) {
                float4 zv = z4[(size_t)gr * (D / 4) + c4];
                float4 av = a4[(size_t)gr * (D / 4) + c4];
                hv.x = fmaf(onePlusEps, zv.x, av.x);
                hv.y = fmaf(onePlusEps, zv.y, av.y);
                hv.z = fmaf(onePlusEps, zv.z, av.z);
                hv.w = fmaf(onePlusEps, zv.w, av.w);
            }
            h4[f] = hv;
        }
#pragma unroll
        for (int t = 0; t < 64; t++) {
            int idx = tid + t * 256;    // 0..16383
            int k = idx >> 7, n = idx & 127;
            sWT[n * WT_STRIDE + k] = __ldg(&W1[idx]);
        }
    }
    __syncthreads();

    // Stage 2: T = relu(h @ W1 + b1)
    float acc[8][4];
#pragma unroll
    for (int i = 0; i < 8; i++)
#pragma unroll
        for (int j = 0; j < 4; j++) acc[i][j] = 0.f;

#pragma unroll 8
    for (int k4 = 0; k4 < D / 4; k4++) {
        float4 wv[4];
#pragma unroll
        for (int j = 0; j < 4; j++)
            wv[j] = *(const float4*)&sWT[(tx + 32 * j) * WT_STRIDE + k4 * 4];
#pragma unroll
        for (int i = 0; i < 8; i++) {
            float4 hv = *(const float4*)&sH[(ty + 8 * i) * D + k4 * 4];
#pragma unroll
            for (int j = 0; j < 4; j++) {
                acc[i][j] = fmaf(hv.x, wv[j].x, acc[i][j]);
                acc[i][j] = fmaf(hv.y, wv[j].y, acc[i][j]);
                acc[i][j] = fmaf(hv.z, wv[j].z, acc[i][j]);
                acc[i][j] = fmaf(hv.w, wv[j].w, acc[i][j]);
            }
        }
    }
    __syncthreads();   // done reading sH/sWT

    // Write T over sH; load W2^T over sWT
    {
        float bj[4];
#pragma unroll
        for (int j = 0; j < 4; j++) bj[j] = __ldg(&b1[tx + 32 * j]);
#pragma unroll
        for (int i = 0; i < 8; i++)
#pragma unroll
            for (int j = 0; j < 4; j++)
                sH[(ty + 8 * i) * D + tx + 32 * j] = fmaxf(acc[i][j] + bj[j], 0.f);
#pragma unroll
        for (int t = 0; t < 64; t++) {
            int idx = tid + t * 256;
            int k = idx >> 7, n = idx & 127;
            sWT[n * WT_STRIDE + k] = __ldg(&W2[idx]);
        }
    }
    __syncthreads();

    // Stage 3: z_new = relu(T @ W2 + b2) -> g_z
#pragma unroll
    for (int i = 0; i < 8; i++)
#pragma unroll
        for (int j = 0; j < 4; j++) acc[i][j] = 0.f;

#pragma unroll 8
    for (int k4 = 0; k4 < D / 4; k4++) {
        float4 wv[4];
#pragma unroll
        for (int j = 0; j < 4; j++)
            wv[j] = *(const float4*)&sWT[(tx + 32 * j) * WT_STRIDE + k4 * 4];
#pragma unroll
        for (int i = 0; i < 8; i++) {
            float4 hv = *(const float4*)&sH[(ty + 8 * i) * D + k4 * 4];
#pragma unroll
            for (int j = 0; j < 4; j++) {
                acc[i][j] = fmaf(hv.x, wv[j].x, acc[i][j]);
                acc[i][j] = fmaf(hv.y, wv[j].y, acc[i][j]);
                acc[i][j] = fmaf(hv.z, wv[j].z, acc[i][j]);
                acc[i][j] = fmaf(hv.w, wv[j].w, acc[i][j]);
            }
        }
    }
    {
        float bj[4];
#pragma unroll
        for (int j = 0; j < 4; j++) bj[j] = __ldg(&b2[tx + 32 * j]);
        float colS[4] = {0.f, 0.f, 0.f, 0.f};
        float colSS[4] = {0.f, 0.f, 0.f, 0.f};
#pragma unroll
        for (int i = 0; i < 8; i++) {
            int gr = row0 + ty + 8 * i;
            if (gr < N_NODES) {
#pragma unroll
                for (int j = 0; j < 4; j++) {
                    float v = fmaxf(acc[i][j] + bj[j], 0.f);
                    g_z[(size_t)gr * D + tx + 32 * j] = v;
                    colS[j] += v;
                    colSS[j] += v * v;
                }
            }
        }
        // BN statistics epilogue (final layer only): tile reduce + 2 atomics/col
        if (layer == 2) {
            __syncthreads();   // sWT no longer needed; reuse as reduce buffer
#pragma unroll
            for (int j = 0; j < 4; j++) {
                sWT[ty * 128 + tx + 32 * j] = colS[j];
                sWT[1024 + ty * 128 + tx + 32 * j] = colSS[j];
            }
            __syncthreads();
            if (tid < 128) {
                float s = 0.f;
#pragma unroll
                for (int w = 0; w < 8; w++) s += sWT[w * 128 + tid];
                atomicAdd(&g_stats[tid], s);
            } else {
                int c = tid - 128;
                float ss = 0.f;
#pragma unroll
                for (int w = 0; w < 8; w++) ss += sWT[1024 + w * 128 + c];
                atomicAdd(&g_stats[D + c], ss);
            }
        }
    }
}

// ---------------------------------------------------------------------------
// Fused BN-normalize (writes zn) + projection GEMM + PReLU (writes p),
// crossbar-optimized 64-row tiling with transposed Wp in smem.
// ---------------------------------------------------------------------------
__global__ void proj_kernel(const float* __restrict__ Wp,
                            const float* __restrict__ bp,
                            const float* __restrict__ gamma,
                            const float* __restrict__ beta,
                            const float* __restrict__ prelu_a,
                            float* __restrict__ out) {
    extern __shared__ float sm[];
    float* sWT = sm;              // 16896
    float* sH  = sm + 16896;      // 8192
    float* sScale = sm + 25088;   // 128
    float* sShift = sm + 25216;   // 128  -> total 25344 floats = 101376 B

    int tid = threadIdx.x;
    int ty = tid >> 5, tx = tid & 31;
    int row0 = blockIdx.x * MT_R;

    if (tid < D) {
        float mean = g_stats[tid] * (1.f / N_NODES);
        float var = g_stats[D + tid] * (1.f / N_NODES) - mean * mean;
        float rs = rsqrtf(var + BN_EPS);
        float sc = __ldg(&gamma[tid]) * rs;
        sScale[tid] = sc;
        sShift[tid] = __ldg(&beta[tid]) - mean * sc;
    }
#pragma unroll
    for (int t = 0; t < 64; t++) {
        int idx = tid + t * 256;
        int k = idx >> 7, n = idx & 127;
        sWT[n * WT_STRIDE + k] = __ldg(&Wp[idx]);
    }
    __syncthreads();

    float* zn_out = out;
    float* p_out = out + (size_t)N_NODES * D;

    // Stage 1: normalize -> zn (global) and sH
    {
        const float4* z4 = (const float4*)g_z;
        float4* h4 = (float4*)sH;
#pragma unroll
        for (int t = 0; t < 8; t++) {
            int f = tid + t * 256;
            int r = f >> 5;
            int c4 = f & 31;
            int gr = row0 + r;
            float4 hv = make_float4(0.f, 0.f, 0.f, 0.f);
            if (gr < N_NODES) {
                float4 zv = z4[(size_t)gr * (D / 4) + c4];
                int c = c4 * 4;
                hv.x = fmaf(zv.x, sScale[c + 0], sShift[c + 0]);
                hv.y = fmaf(zv.y, sScale[c + 1], sShift[c + 1]);
                hv.z = fmaf(zv.z, sScale[c + 2], sShift[c + 2]);
                hv.w = fmaf(zv.w, sScale[c + 3], sShift[c + 3]);
                ((float4*)zn_out)[(size_t)gr * (D / 4) + c4] = hv;
            }
            h4[f] = hv;
        }
    }
    __syncthreads();

    // Stage 2: p = prelu(zn @ Wp + bp)
    float acc[8][4];
#pragma unroll
    for (int i = 0; i < 8; i++)
#pragma unroll
        for (int j = 0; j < 4; j++) acc[i][j] = 0.f;

#pragma unroll 8
    for (int k4 = 0; k4 < D / 4; k4++) {
        float4 wv[4];
#pragma unroll
        for (int j = 0; j < 4; j++)
            wv[j] = *(const float4*)&sWT[(tx + 32 * j) * WT_STRIDE + k4 * 4];
#pragma unroll
        for (int i = 0; i < 8; i++) {
            float4 hv = *(const float4*)&sH[(ty + 8 * i) * D + k4 * 4];
#pragma unroll
            for (int j = 0; j < 4; j++) {
                acc[i][j] = fmaf(hv.x, wv[j].x, acc[i][j]);
                acc[i][j] = fmaf(hv.y, wv[j].y, acc[i][j]);
                acc[i][j] = fmaf(hv.z, wv[j].z, acc[i][j]);
                acc[i][j] = fmaf(hv.w, wv[j].w, acc[i][j]);
            }
        }
    }
    {
        float a = __ldg(&prelu_a[0]);
        float bj[4];
#pragma unroll
        for (int j = 0; j < 4; j++) bj[j] = __ldg(&bp[tx + 32 * j]);
#pragma unroll
        for (int i = 0; i < 8; i++) {
            int gr = row0 + ty + 8 * i;
            if (gr < N_NODES) {
#pragma unroll
                for (int j = 0; j < 4; j++) {
                    float v = acc[i][j] + bj[j];
                    p_out[(size_t)gr * D + tx + 32 * j] = (v >= 0.f) ? v : a * v;
                }
            }
        }
    }
}

// ---------------------------------------------------------------------------
extern "C" void kernel_launch(void* const* d_in, const int* in_sizes, int n_in,
                              void* d_out, int out_size) {
    const float* x       = (const float*)d_in[0];
    const float* ew      = (const float*)d_in[1];
    const float* W1s     = (const float*)d_in[2];
    const float* b1s     = (const float*)d_in[3];
    const float* W2s     = (const float*)d_in[4];
    const float* b2s     = (const float*)d_in[5];
    const float* eps     = (const float*)d_in[6];
    const float* gamma   = (const float*)d_in[7];
    const float* beta    = (const float*)d_in[8];
    const float* Wp      = (const float*)d_in[9];
    const float* bp      = (const float*)d_in[10];
    const float* prelu_a = (const float*)d_in[11];
    const int*   ei32    = (const int*)d_in[12];
    float* out = (float*)d_out;

    cudaFuncSetAttribute(mlp_kernel, cudaFuncAttributeMaxDynamicSharedMemorySize, 100352);
    cudaFuncSetAttribute(proj_kernel, cudaFuncAttributeMaxDynamicSharedMemorySize, 101376);

    const int edgeBlocks = (N_EDGES + 255) / 256;           // 3125
    const int mlpBlocks  = (N_NODES + MT_R - 1) / MT_R;     // 782
    const int aggBlocks  = (N_NODES * 32 + 255) / 256;      // 6250
    const int nodeBlocks = (N_NODES + 255) / 256;           // 196

    // Build CSR once per call (reused by all 3 layers)
    zero_counters_kernel<<<nodeBlocks, 256>>>(ei32);
    hist_kernel<<<edgeBlocks, 256>>>(ei32);
    scan_partial_kernel<<<N_CHUNKS, SCAN_CHUNK>>>();
    scan_part_kernel<<<1, 128>>>();
    scan_add_kernel<<<nodeBlocks, 256>>>();
    scatter_kernel<<<edgeBlocks, 256>>>(ew, ei32);

    for (int l = 0; l < 3; l++) {
        agg_kernel<<<aggBlocks, 256>>>(x, l == 0 ? 1 : 0);
        mlp_kernel<<<mlpBlocks, 256, 100352>>>(x, W1s, b1s, W2s, b2s, eps, l);
    }
    proj_kernel<<<mlpBlocks, 256, 101376>>>(Wp, bp, gamma, beta, prelu_a, out);
}

// round 10
// speedup vs baseline: 1.4820x; 1.0181x over previous
#include <cuda_runtime.h>

#define N_NODES 50000
#define N_EDGES 800000
#define D 128
#define BN_EPS 1e-5f
#define MT_R 64       // mlp/proj tile rows
#define SCAN_CHUNK 512
#define N_CHUNKS ((N_NODES + SCAN_CHUNK - 1) / SCAN_CHUNK)   // 98
#define WT_STRIDE 132

// Packed fp32x2 FMA: d = a*b + c elementwise on two packed floats.
#define FFMA2(d, a, b, c) \
    asm("fma.rn.f32x2 %0, %1, %2, %3;" : "=l"(d) : "l"(a), "l"(b), "l"(c))

__device__ __forceinline__ float hadd2(unsigned long long p) {
    float lo, hi;
    asm("mov.b64 {%0, %1}, %2;" : "=f"(lo), "=f"(hi) : "l"(p));
    return lo + hi;
}

// Persistent scratch (static device allocation — allowed; runtime alloc is not).
__device__ __align__(16) float g_z[N_NODES * D];    // current node features
__device__ __align__(16) float g_agg[N_NODES * D];  // aggregation result
__device__ float g_stats[2 * D];                    // BN col sum / sumsq
__device__ int g_idx64;                             // 1 if edge_index is int64
__device__ int g_deg[N_NODES];                      // degree histogram
__device__ int g_cur[N_NODES];                      // scatter cursors (=rowptr)
__device__ int g_rowptr[N_NODES + 1];               // CSR row pointers
__device__ int g_part[N_CHUNKS];                    // chunk totals for scan
__device__ int g_esrc[N_EDGES];                     // CSR: src per slot
__device__ __align__(16) float g_ewt[N_EDGES];      // CSR: weight per slot

// ---------------------------------------------------------------------------
// Zero counters + BN stats; block 0 thread 0 also probes edge_index dtype.
// ---------------------------------------------------------------------------
__global__ void zero_counters_kernel(const int* __restrict__ ei32) {
    int i = blockIdx.x * blockDim.x + threadIdx.x;
    if (i < N_NODES) g_deg[i] = 0;
    if (i < 2 * D) g_stats[i] = 0.f;
    if (i == 0) {
        int all_zero = 1;
#pragma unroll
        for (int k = 0; k < 64; k++)
            if (__ldg(&ei32[2 * k + 1]) != 0) all_zero = 0;
        g_idx64 = all_zero;
    }
}

__device__ __forceinline__ int load_src(const int* ei32, int e) {
    int s = g_idx64 ? __ldg(&ei32[2 * e]) : __ldg(&ei32[e]);
    return min(max(s, 0), N_NODES - 1);
}
__device__ __forceinline__ int load_dst(const int* ei32, int e) {
    int d = g_idx64 ? __ldg(&ei32[2 * N_EDGES + 2 * e]) : __ldg(&ei32[N_EDGES + e]);
    return min(max(d, 0), N_NODES - 1);
}

__global__ void hist_kernel(const int* __restrict__ ei32) {
    int e = blockIdx.x * blockDim.x + threadIdx.x;
    if (e >= N_EDGES) return;
    atomicAdd(&g_deg[load_dst(ei32, e)], 1);
}

// Phase 1: per-chunk exclusive scan (chunk = 512) + chunk total.
__global__ void scan_partial_kernel() {
    __shared__ int wsum[16];
    int tid = threadIdx.x, lane = tid & 31, wid = tid >> 5;
    int i = blockIdx.x * SCAN_CHUNK + tid;
    int v = (i < N_NODES) ? g_deg[i] : 0;
    int x = v;
#pragma unroll
    for (int o = 1; o < 32; o <<= 1) {
        int y = __shfl_up_sync(0xFFFFFFFFu, x, o);
        if (lane >= o) x += y;
    }
    if (lane == 31) wsum[wid] = x;
    __syncthreads();
    if (wid == 0 && lane < 16) {
        int w = wsum[lane];
#pragma unroll
        for (int o = 1; o < 16; o <<= 1) {
            int y = __shfl_up_sync(0x0000FFFFu, w, o);
            if (lane >= o) w += y;
        }
        wsum[lane] = w;
    }
    __syncthreads();
    int base = (wid > 0) ? wsum[wid - 1] : 0;
    if (i < N_NODES) g_rowptr[i] = base + x - v;
    if (tid == SCAN_CHUNK - 1) g_part[blockIdx.x] = base + x;
}

// Phase 2: single small block scans the 98 chunk totals (exclusive) + total.
__global__ void scan_part_kernel() {
    __shared__ int wsum[4];
    int tid = threadIdx.x, lane = tid & 31, wid = tid >> 5;   // 128 threads
    int v = (tid < N_CHUNKS) ? g_part[tid] : 0;
    int x = v;
#pragma unroll
    for (int o = 1; o < 32; o <<= 1) {
        int y = __shfl_up_sync(0xFFFFFFFFu, x, o);
        if (lane >= o) x += y;
    }
    if (lane == 31) wsum[wid] = x;
    __syncthreads();
    int base = 0;
    for (int w = 0; w < wid; w++) base += wsum[w];
    __syncthreads();
    if (tid < N_CHUNKS) g_part[tid] = base + x - v;
    if (tid == N_CHUNKS - 1) g_rowptr[N_NODES] = base + x;
}

// Phase 3: add chunk offsets; init scatter cursors to rowptr.
__global__ void scan_add_kernel() {
    int i = blockIdx.x * blockDim.x + threadIdx.x;
    if (i >= N_NODES) return;
    int r = g_rowptr[i] + g_part[i >> 9];
    g_rowptr[i] = r;
    g_cur[i] = r;
}

__global__ void scatter_kernel(const float* __restrict__ ew,
                               const int* __restrict__ ei32) {
    int e = blockIdx.x * blockDim.x + threadIdx.x;
    if (e >= N_EDGES) return;
    int src = load_src(ei32, e);
    int dst = load_dst(ei32, e);
    int pos = atomicAdd(&g_cur[dst], 1);
    g_esrc[pos] = src;
    g_ewt[pos] = __ldg(&ew[e]);
}

// ---------------------------------------------------------------------------
// CSR aggregation: one warp per node, register accumulation, no atomics.
// ---------------------------------------------------------------------------
__global__ void agg_kernel(const float* __restrict__ xin, int use_x) {
    int node = (blockIdx.x * blockDim.x + threadIdx.x) >> 5;
    if (node >= N_NODES) return;
    int lane = threadIdx.x & 31;
    const float* z = use_x ? xin : g_z;

    int beg = __ldg(&g_rowptr[node]);
    int end = __ldg(&g_rowptr[node + 1]);
    float4 acc = make_float4(0.f, 0.f, 0.f, 0.f);
    int e = beg;
    for (; e + 4 <= end; e += 4) {
        int s0 = __ldg(&g_esrc[e]);
        int s1 = __ldg(&g_esrc[e + 1]);
        int s2 = __ldg(&g_esrc[e + 2]);
        int s3 = __ldg(&g_esrc[e + 3]);
        float w0 = __ldg(&g_ewt[e]);
        float w1 = __ldg(&g_ewt[e + 1]);
        float w2 = __ldg(&g_ewt[e + 2]);
        float w3 = __ldg(&g_ewt[e + 3]);
        float4 v0 = ((const float4*)(z + (size_t)s0 * D))[lane];
        float4 v1 = ((const float4*)(z + (size_t)s1 * D))[lane];
        float4 v2 = ((const float4*)(z + (size_t)s2 * D))[lane];
        float4 v3 = ((const float4*)(z + (size_t)s3 * D))[lane];
        acc.x = fmaf(v0.x, w0, acc.x); acc.y = fmaf(v0.y, w0, acc.y);
        acc.z = fmaf(v0.z, w0, acc.z); acc.w = fmaf(v0.w, w0, acc.w);
        acc.x = fmaf(v1.x, w1, acc.x); acc.y = fmaf(v1.y, w1, acc.y);
        acc.z = fmaf(v1.z, w1, acc.z); acc.w = fmaf(v1.w, w1, acc.w);
        acc.x = fmaf(v2.x, w2, acc.x); acc.y = fmaf(v2.y, w2, acc.y);
        acc.z = fmaf(v2.z, w2, acc.z); acc.w = fmaf(v2.w, w2, acc.w);
        acc.x = fmaf(v3.x, w3, acc.x); acc.y = fmaf(v3.y, w3, acc.y);
        acc.z = fmaf(v3.z, w3, acc.z); acc.w = fmaf(v3.w, w3, acc.w);
    }
    for (; e < end; e++) {
        int s0 = __ldg(&g_esrc[e]);
        float w0 = __ldg(&g_ewt[e]);
        float4 v0 = ((const float4*)(z + (size_t)s0 * D))[lane];
        acc.x = fmaf(v0.x, w0, acc.x); acc.y = fmaf(v0.y, w0, acc.y);
        acc.z = fmaf(v0.z, w0, acc.z); acc.w = fmaf(v0.w, w0, acc.w);
    }
    ((float4*)(g_agg + (size_t)node * D))[lane] = acc;
}

// ---------------------------------------------------------------------------
// GEMM core macro: f32x2-packed over k. acc2[i][j] holds (even-k, odd-k) sums.
// ---------------------------------------------------------------------------
#define GEMM_F32X2(sH_, sWT_, acc2_)                                          \
    do {                                                                      \
        _Pragma("unroll 4")                                                   \
        for (int k4 = 0; k4 < D / 4; k4++) {                                  \
            ulonglong2 wv[4];                                                 \
            _Pragma("unroll")                                                 \
            for (int j = 0; j < 4; j++)                                       \
                wv[j] = *(const ulonglong2*)&sWT_[(tx + 32 * j) * WT_STRIDE + k4 * 4]; \
            _Pragma("unroll")                                                 \
            for (int i = 0; i < 8; i++) {                                     \
                ulonglong2 hv = *(const ulonglong2*)&sH_[(ty + 8 * i) * D + k4 * 4]; \
                _Pragma("unroll")                                             \
                for (int j = 0; j < 4; j++) {                                 \
                    FFMA2(acc2_[i][j], hv.x, wv[j].x, acc2_[i][j]);           \
                    FFMA2(acc2_[i][j], hv.y, wv[j].y, acc2_[i][j]);           \
                }                                                             \
            }                                                                 \
        }                                                                     \
    } while (0)

// ---------------------------------------------------------------------------
// Fused GIN node update + 2-layer MLP (f32x2 GEMMs). On layer 2, the epilogue
// also accumulates BN column sums/sumsqs (tile-reduce + 2 atomics/col).
// ---------------------------------------------------------------------------
__global__ void __launch_bounds__(256, 2)
mlp_kernel(const float* __restrict__ xin,
           const float* __restrict__ W1s,
           const float* __restrict__ b1s,
           const float* __restrict__ W2s,
           const float* __restrict__ b2s,
           const float* __restrict__ epsp,
           int layer) {
    extern __shared__ float sm[];
    float* sWT = sm;                    // 128*132 = 16896 floats
    float* sH  = sm + 16896;            // 64*128  =  8192 floats

    const float* zin = (layer == 0) ? xin : g_z;
    const float* W1 = W1s + layer * D * D;
    const float* W2 = W2s + layer * D * D;
    const float* b1 = b1s + layer * D;
    const float* b2 = b2s + layer * D;
    const float onePlusEps = 1.f + __ldg(&epsp[layer]);

    int tid = threadIdx.x;
    int ty = tid >> 5;    // warp id 0..7 -> base row
    int tx = tid & 31;    // lane -> base col
    int row0 = blockIdx.x * MT_R;

    // Stage 1: h tile -> sH ; W1^T -> sWT
    {
        const float4* z4 = (const float4*)zin;
        const float4* a4 = (const float4*)g_agg;
        float4* h4 = (float4*)sH;
#pragma unroll
        for (int t = 0; t < 8; t++) {
            int f = tid + t * 256;      // 0..2047
            int r = f >> 5;
            int c4 = f & 31;
            int gr = row0 + r;
            float4 hv = make_float4(0.f, 0.f, 0.f, 0.f);
            if (gr < N_NODES) {
                float4 zv = z4[(size_t)gr * (D / 4) + c4];
                float4 av = a4[(size_t)gr * (D / 4) + c4];
                hv.x = fmaf(onePlusEps, zv.x, av.x);
                hv.y = fmaf(onePlusEps, zv.y, av.y);
                hv.z = fmaf(onePlusEps, zv.z, av.z);
                hv.w = fmaf(onePlusEps, zv.w, av.w);
            }
            h4[f] = hv;
        }
#pragma unroll
        for (int t = 0; t < 64; t++) {
            int idx = tid + t * 256;    // 0..16383
            int k = idx >> 7, n = idx & 127;
            sWT[n * WT_STRIDE + k] = __ldg(&W1[idx]);
        }
    }
    __syncthreads();

    // Stage 2: T = relu(h @ W1 + b1)
    unsigned long long acc2[8][4];
#pragma unroll
    for (int i = 0; i < 8; i++)
#pragma unroll
        for (int j = 0; j < 4; j++) acc2[i][j] = 0ULL;

    GEMM_F32X2(sH, sWT, acc2);
    __syncthreads();   // done reading sH/sWT

    // Write T over sH; load W2^T over sWT
    {
        float bj[4];
#pragma unroll
        for (int j = 0; j < 4; j++) bj[j] = __ldg(&b1[tx + 32 * j]);
#pragma unroll
        for (int i = 0; i < 8; i++)
#pragma unroll
            for (int j = 0; j < 4; j++)
                sH[(ty + 8 * i) * D + tx + 32 * j] =
                    fmaxf(hadd2(acc2[i][j]) + bj[j], 0.f);
#pragma unroll
        for (int t = 0; t < 64; t++) {
            int idx = tid + t * 256;
            int k = idx >> 7, n = idx & 127;
            sWT[n * WT_STRIDE + k] = __ldg(&W2[idx]);
        }
    }
    __syncthreads();

    // Stage 3: z_new = relu(T @ W2 + b2) -> g_z
#pragma unroll
    for (int i = 0; i < 8; i++)
#pragma unroll
        for (int j = 0; j < 4; j++) acc2[i][j] = 0ULL;

    GEMM_F32X2(sH, sWT, acc2);

    {
        float bj[4];
#pragma unroll
        for (int j = 0; j < 4; j++) bj[j] = __ldg(&b2[tx + 32 * j]);
        float colS[4] = {0.f, 0.f, 0.f, 0.f};
        float colSS[4] = {0.f, 0.f, 0.f, 0.f};
#pragma unroll
        for (int i = 0; i < 8; i++) {
            int gr = row0 + ty + 8 * i;
            if (gr < N_NODES) {
#pragma unroll
                for (int j = 0; j < 4; j++) {
                    float v = fmaxf(hadd2(acc2[i][j]) + bj[j], 0.f);
                    g_z[(size_t)gr * D + tx + 32 * j] = v;
                    colS[j] += v;
                    colSS[j] += v * v;
                }
            }
        }
        // BN statistics epilogue (final layer only)
        if (layer == 2) {
            __syncthreads();   // sWT no longer needed; reuse as reduce buffer
#pragma unroll
            for (int j = 0; j < 4; j++) {
                sWT[ty * 128 + tx + 32 * j] = colS[j];
                sWT[1024 + ty * 128 + tx + 32 * j] = colSS[j];
            }
            __syncthreads();
            if (tid < 128) {
                float s = 0.f;
#pragma unroll
                for (int w = 0; w < 8; w++) s += sWT[w * 128 + tid];
                atomicAdd(&g_stats[tid], s);
            } else {
                int c = tid - 128;
                float ss = 0.f;
#pragma unroll
                for (int w = 0; w < 8; w++) ss += sWT[1024 + w * 128 + c];
                atomicAdd(&g_stats[D + c], ss);
            }
        }
    }
}

// ---------------------------------------------------------------------------
// Fused BN-normalize (writes zn) + projection GEMM + PReLU (writes p).
// ---------------------------------------------------------------------------
__global__ void __launch_bounds__(256, 2)
proj_kernel(const float* __restrict__ Wp,
            const float* __restrict__ bp,
            const float* __restrict__ gamma,
            const float* __restrict__ beta,
            const float* __restrict__ prelu_a,
            float* __restrict__ out) {
    extern __shared__ float sm[];
    float* sWT = sm;              // 16896
    float* sH  = sm + 16896;      // 8192
    float* sScale = sm + 25088;   // 128
    float* sShift = sm + 25216;   // 128  -> total 25344 floats = 101376 B

    int tid = threadIdx.x;
    int ty = tid >> 5, tx = tid & 31;
    int row0 = blockIdx.x * MT_R;

    if (tid < D) {
        float mean = g_stats[tid] * (1.f / N_NODES);
        float var = g_stats[D + tid] * (1.f / N_NODES) - mean * mean;
        float rs = rsqrtf(var + BN_EPS);
        float sc = __ldg(&gamma[tid]) * rs;
        sScale[tid] = sc;
        sShift[tid] = __ldg(&beta[tid]) - mean * sc;
    }
#pragma unroll
    for (int t = 0; t < 64; t++) {
        int idx = tid + t * 256;
        int k = idx >> 7, n = idx & 127;
        sWT[n * WT_STRIDE + k] = __ldg(&Wp[idx]);
    }
    __syncthreads();

    float* zn_out = out;
    float* p_out = out + (size_t)N_NODES * D;

    // Stage 1: normalize -> zn (global) and sH
    {
        const float4* z4 = (const float4*)g_z;
        float4* h4 = (float4*)sH;
#pragma unroll
        for (int t = 0; t < 8; t++) {
            int f = tid + t * 256;
            int r = f >> 5;
            int c4 = f & 31;
            int gr = row0 + r;
            float4 hv = make_float4(0.f, 0.f, 0.f, 0.f);
            if (gr < N_NODES) {
                float4 zv = z4[(size_t)gr * (D / 4) + c4];
                int c = c4 * 4;
                hv.x = fmaf(zv.x, sScale[c + 0], sShift[c + 0]);
                hv.y = fmaf(zv.y, sScale[c + 1], sShift[c + 1]);
                hv.z = fmaf(zv.z, sScale[c + 2], sShift[c + 2]);
                hv.w = fmaf(zv.w, sScale[c + 3], sShift[c + 3]);
                ((float4*)zn_out)[(size_t)gr * (D / 4) + c4] = hv;
            }
            h4[f] = hv;
        }
    }
    __syncthreads();

    // Stage 2: p = prelu(zn @ Wp + bp)
    unsigned long long acc2[8][4];
#pragma unroll
    for (int i = 0; i < 8; i++)
#pragma unroll
        for (int j = 0; j < 4; j++) acc2[i][j] = 0ULL;

    GEMM_F32X2(sH, sWT, acc2);

    {
        float a = __ldg(&prelu_a[0]);
        float bj[4];
#pragma unroll
        for (int j = 0; j < 4; j++) bj[j] = __ldg(&bp[tx + 32 * j]);
#pragma unroll
        for (int i = 0; i < 8; i++) {
            int gr = row0 + ty + 8 * i;
            if (gr < N_NODES) {
#pragma unroll
                for (int j = 0; j < 4; j++) {
                    float v = hadd2(acc2[i][j]) + bj[j];
                    p_out[(size_t)gr * D + tx + 32 * j] = (v >= 0.f) ? v : a * v;
                }
            }
        }
    }
}

// ---------------------------------------------------------------------------
extern "C" void kernel_launch(void* const* d_in, const int* in_sizes, int n_in,
                              void* d_out, int out_size) {
    const float* x       = (const float*)d_in[0];
    const float* ew      = (const float*)d_in[1];
    const float* W1s     = (const float*)d_in[2];
    const float* b1s     = (const float*)d_in[3];
    const float* W2s     = (const float*)d_in[4];
    const float* b2s     = (const float*)d_in[5];
    const float* eps     = (const float*)d_in[6];
    const float* gamma   = (const float*)d_in[7];
    const float* beta    = (const float*)d_in[8];
    const float* Wp      = (const float*)d_in[9];
    const float* bp      = (const float*)d_in[10];
    const float* prelu_a = (const float*)d_in[11];
    const int*   ei32    = (const int*)d_in[12];
    float* out = (float*)d_out;

    cudaFuncSetAttribute(mlp_kernel, cudaFuncAttributeMaxDynamicSharedMemorySize, 100352);
    cudaFuncSetAttribute(proj_kernel, cudaFuncAttributeMaxDynamicSharedMemorySize, 101376);

    const int edgeBlocks = (N_EDGES + 255) / 256;           // 3125
    const int mlpBlocks  = (N_NODES + MT_R - 1) / MT_R;     // 782
    const int aggBlocks  = (N_NODES * 32 + 255) / 256;      // 6250
    const int nodeBlocks = (N_NODES + 255) / 256;           // 196

    // Build CSR once per call (reused by all 3 layers)
    zero_counters_kernel<<<nodeBlocks, 256>>>(ei32);
    hist_kernel<<<edgeBlocks, 256>>>(ei32);
    scan_partial_kernel<<<N_CHUNKS, SCAN_CHUNK>>>();
    scan_part_kernel<<<1, 128>>>();
    scan_add_kernel<<<nodeBlocks, 256>>>();
    scatter_kernel<<<edgeBlocks, 256>>>(ew, ei32);

    for (int l = 0; l < 3; l++) {
        agg_kernel<<<aggBlocks, 256>>>(x, l == 0 ? 1 : 0);
        mlp_kernel<<<mlpBlocks, 256, 100352>>>(x, W1s, b1s, W2s, b2s, eps, l);
    }
    proj_kernel<<<mlpBlocks, 256, 101376>>>(Wp, bp, gamma, beta, prelu_a, out);
}

// round 13
// speedup vs baseline: 1.8845x; 1.2716x over previous
#include <cuda_runtime.h>
#include <cuda_fp16.h>
#include <cstdint>

#define N_NODES 50000
#define N_EDGES 800000
#define D 128
#define BN_EPS 1e-5f
#define SCAN_CHUNK 512
#define N_CHUNKS ((N_NODES + SCAN_CHUNK - 1) / SCAN_CHUNK)   // 98
#define SA 136                      // half stride for A/WT tiles (272B rows)
#define TILE_BYTES (128 * SA * 2)   // 34816
#define SM_AHI 0
#define SM_ALO TILE_BYTES           // 34816
#define SM_WT  (2 * TILE_BYTES)     // 69632
#define SM_MLP_TOTAL (3 * TILE_BYTES)         // 104448
#define SM_SC  SM_MLP_TOTAL
#define SM_PROJ_TOTAL (SM_MLP_TOTAL + 1024)   // +256 floats scale/shift

// Persistent scratch.
__device__ __align__(16) float g_z[N_NODES * D];
__device__ __align__(16) float g_agg[N_NODES * D];
__device__ float g_stats[2 * D];
__device__ int g_idx64;
__device__ int g_deg[N_NODES];
__device__ int g_cur[N_NODES];
__device__ int g_rowptr[N_NODES + 1];
__device__ int g_part[N_CHUNKS];
__device__ int g_esrc[N_EDGES];
__device__ __align__(16) float g_ewt[N_EDGES];

// ===========================================================================
// CSR build (unchanged, passing since round 8)
// ===========================================================================
__global__ void zero_counters_kernel(const int* __restrict__ ei32) {
    int i = blockIdx.x * blockDim.x + threadIdx.x;
    if (i < N_NODES) g_deg[i] = 0;
    if (i < 2 * D) g_stats[i] = 0.f;
    if (i == 0) {
        int all_zero = 1;
#pragma unroll
        for (int k = 0; k < 64; k++)
            if (__ldg(&ei32[2 * k + 1]) != 0) all_zero = 0;
        g_idx64 = all_zero;
    }
}

__device__ __forceinline__ int load_src(const int* ei32, int e) {
    int s = g_idx64 ? __ldg(&ei32[2 * e]) : __ldg(&ei32[e]);
    return min(max(s, 0), N_NODES - 1);
}
__device__ __forceinline__ int load_dst(const int* ei32, int e) {
    int d = g_idx64 ? __ldg(&ei32[2 * N_EDGES + 2 * e]) : __ldg(&ei32[N_EDGES + e]);
    return min(max(d, 0), N_NODES - 1);
}

__global__ void hist_kernel(const int* __restrict__ ei32) {
    int e = blockIdx.x * blockDim.x + threadIdx.x;
    if (e >= N_EDGES) return;
    atomicAdd(&g_deg[load_dst(ei32, e)], 1);
}

__global__ void scan_partial_kernel() {
    __shared__ int wsum[16];
    int tid = threadIdx.x, lane = tid & 31, wid = tid >> 5;
    int i = blockIdx.x * SCAN_CHUNK + tid;
    int v = (i < N_NODES) ? g_deg[i] : 0;
    int x = v;
#pragma unroll
    for (int o = 1; o < 32; o <<= 1) {
        int y = __shfl_up_sync(0xFFFFFFFFu, x, o);
        if (lane >= o) x += y;
    }
    if (lane == 31) wsum[wid] = x;
    __syncthreads();
    if (wid == 0 && lane < 16) {
        int w = wsum[lane];
#pragma unroll
        for (int o = 1; o < 16; o <<= 1) {
            int y = __shfl_up_sync(0x0000FFFFu, w, o);
            if (lane >= o) w += y;
        }
        wsum[lane] = w;
    }
    __syncthreads();
    int base = (wid > 0) ? wsum[wid - 1] : 0;
    if (i < N_NODES) g_rowptr[i] = base + x - v;
    if (tid == SCAN_CHUNK - 1) g_part[blockIdx.x] = base + x;
}

__global__ void scan_part_kernel() {
    __shared__ int wsum[4];
    int tid = threadIdx.x, lane = tid & 31, wid = tid >> 5;
    int v = (tid < N_CHUNKS) ? g_part[tid] : 0;
    int x = v;
#pragma unroll
    for (int o = 1; o < 32; o <<= 1) {
        int y = __shfl_up_sync(0xFFFFFFFFu, x, o);
        if (lane >= o) x += y;
    }
    if (lane == 31) wsum[wid] = x;
    __syncthreads();
    int base = 0;
    for (int w = 0; w < wid; w++) base += wsum[w];
    __syncthreads();
    if (tid < N_CHUNKS) g_part[tid] = base + x - v;
    if (tid == N_CHUNKS - 1) g_rowptr[N_NODES] = base + x;
}

__global__ void scan_add_kernel() {
    int i = blockIdx.x * blockDim.x + threadIdx.x;
    if (i >= N_NODES) return;
    int r = g_rowptr[i] + g_part[i >> 9];
    g_rowptr[i] = r;
    g_cur[i] = r;
}

__global__ void scatter_kernel(const float* __restrict__ ew,
                               const int* __restrict__ ei32) {
    int e = blockIdx.x * blockDim.x + threadIdx.x;
    if (e >= N_EDGES) return;
    int src = load_src(ei32, e);
    int dst = load_dst(ei32, e);
    int pos = atomicAdd(&g_cur[dst], 1);
    g_esrc[pos] = src;
    g_ewt[pos] = __ldg(&ew[e]);
}

// ===========================================================================
// CSR aggregation (unchanged)
// ===========================================================================
__global__ void agg_kernel(const float* __restrict__ xin, int use_x) {
    int node = (blockIdx.x * blockDim.x + threadIdx.x) >> 5;
    if (node >= N_NODES) return;
    int lane = threadIdx.x & 31;
    const float* z = use_x ? xin : g_z;

    int beg = __ldg(&g_rowptr[node]);
    int end = __ldg(&g_rowptr[node + 1]);
    float4 acc = make_float4(0.f, 0.f, 0.f, 0.f);
    int e = beg;
    for (; e + 4 <= end; e += 4) {
        int s0 = __ldg(&g_esrc[e]);
        int s1 = __ldg(&g_esrc[e + 1]);
        int s2 = __ldg(&g_esrc[e + 2]);
        int s3 = __ldg(&g_esrc[e + 3]);
        float w0 = __ldg(&g_ewt[e]);
        float w1 = __ldg(&g_ewt[e + 1]);
        float w2 = __ldg(&g_ewt[e + 2]);
        float w3 = __ldg(&g_ewt[e + 3]);
        float4 v0 = ((const float4*)(z + (size_t)s0 * D))[lane];
        float4 v1 = ((const float4*)(z + (size_t)s1 * D))[lane];
        float4 v2 = ((const float4*)(z + (size_t)s2 * D))[lane];
        float4 v3 = ((const float4*)(z + (size_t)s3 * D))[lane];
        acc.x = fmaf(v0.x, w0, acc.x); acc.y = fmaf(v0.y, w0, acc.y);
        acc.z = fmaf(v0.z, w0, acc.z); acc.w = fmaf(v0.w, w0, acc.w);
        acc.x = fmaf(v1.x, w1, acc.x); acc.y = fmaf(v1.y, w1, acc.y);
        acc.z = fmaf(v1.z, w1, acc.z); acc.w = fmaf(v1.w, w1, acc.w);
        acc.x = fmaf(v2.x, w2, acc.x); acc.y = fmaf(v2.y, w2, acc.y);
        acc.z = fmaf(v2.z, w2, acc.z); acc.w = fmaf(v2.w, w2, acc.w);
        acc.x = fmaf(v3.x, w3, acc.x); acc.y = fmaf(v3.y, w3, acc.y);
        acc.z = fmaf(v3.z, w3, acc.z); acc.w = fmaf(v3.w, w3, acc.w);
    }
    for (; e < end; e++) {
        int s0 = __ldg(&g_esrc[e]);
        float w0 = __ldg(&g_ewt[e]);
        float4 v0 = ((const float4*)(z + (size_t)s0 * D))[lane];
        acc.x = fmaf(v0.x, w0, acc.x); acc.y = fmaf(v0.y, w0, acc.y);
        acc.z = fmaf(v0.z, w0, acc.z); acc.w = fmaf(v0.w, w0, acc.w);
    }
    ((float4*)(g_agg + (size_t)node * D))[lane] = acc;
}

// ===========================================================================
// HMMA GEMM machinery (mma.sync m16n8k16, fp16 in / fp32 accum)
// Fragment mapping (PTX ISA, g=lane>>2, ti=lane&3):
//   A(16x16 row): a0=(g, 2ti..+1) a1=(g+8, ..) a2=(g, 2ti+8..) a3=(g+8, 2ti+8..)
//   B(16x8 col):  b0=(k=2ti..+1, n=g)  b1=(k=2ti+8..+1, n=g)
//   C(16x8):      c0=(g, 2ti) c1=(g, 2ti+1) c2=(g+8, 2ti) c3=(g+8, 2ti+1)
// Tiles stored [row][k] halves, stride SA=136 -> bank = (4*row + ti) % 32,
// conflict-free for all fragment loads.
// ===========================================================================
__device__ __forceinline__ void mma16816(float* c, uint32_t a0, uint32_t a1,
                                         uint32_t a2, uint32_t a3,
                                         uint32_t b0, uint32_t b1) {
    asm volatile(
        "mma.sync.aligned.m16n8k16.row.col.f32.f16.f16.f32 "
        "{%0,%1,%2,%3}, {%4,%5,%6,%7}, {%8,%9}, {%0,%1,%2,%3};"
        : "+f"(c[0]), "+f"(c[1]), "+f"(c[2]), "+f"(c[3])
        : "r"(a0), "r"(a1), "r"(a2), "r"(a3), "r"(b0), "r"(b1));
}

template <bool DUAL>
__device__ __forceinline__ void gemm_pass(const __half* sAhi, const __half* sAlo,
                                          const __half* sWT, float C[16][4],
                                          int wid, int g, int ti) {
    for (int ks = 0; ks < 8; ks++) {
        int k0 = ks * 16;
        int ra = (wid * 16 + g) * SA + ti * 2 + k0;
        uint32_t h0 = *(const uint32_t*)&sAhi[ra];
        uint32_t h1 = *(const uint32_t*)&sAhi[ra + 8 * SA];
        uint32_t h2 = *(const uint32_t*)&sAhi[ra + 8];
        uint32_t h3 = *(const uint32_t*)&sAhi[ra + 8 * SA + 8];
        uint32_t l0 = 0, l1 = 0, l2 = 0, l3 = 0;
        if (DUAL) {
            l0 = *(const uint32_t*)&sAlo[ra];
            l1 = *(const uint32_t*)&sAlo[ra + 8 * SA];
            l2 = *(const uint32_t*)&sAlo[ra + 8];
            l3 = *(const uint32_t*)&sAlo[ra + 8 * SA + 8];
        }
#pragma unroll
        for (int nt = 0; nt < 16; nt++) {
            int rb = (nt * 8 + g) * SA + ti * 2 + k0;
            uint32_t b0 = *(const uint32_t*)&sWT[rb];
            uint32_t b1 = *(const uint32_t*)&sWT[rb + 8];
            mma16816(C[nt], h0, h1, h2, h3, b0, b1);
            if (DUAL) mma16816(C[nt], l0, l1, l2, l3, b0, b1);
        }
    }
}

// Fill WT[n][k] (stride SA) with hi (part=0) or lo (part=1) half of W[k][n].
__device__ __forceinline__ void fill_wt(const float* __restrict__ W, __half* sWT,
                                        int tid, int part) {
    for (int idx = tid; idx < D * D; idx += 256) {
        int k = idx >> 7, n = idx & 127;
        float w = __ldg(&W[idx]);            // idx = k*128+n
        __half hi = __float2half_rn(w);
        sWT[n * SA + k] = part ? __float2half_rn(w - __half2float(hi)) : hi;
    }
}

__device__ __forceinline__ uint32_t pack_halves(float a, float b) {
    __half ha = __float2half_rn(a), hb = __float2half_rn(b);
    return (uint32_t)__half_as_ushort(ha) | ((uint32_t)__half_as_ushort(hb) << 16);
}

// ===========================================================================
// Fused GIN layer: two chained 128x128x128 GEMMs on HMMA, fp16 hi/lo split
// (3 terms each), fp32 register accumulators. Layer 2 fuses BN statistics.
// ===========================================================================
__global__ void __launch_bounds__(256)
mlp_mma_kernel(const float* __restrict__ xin,
               const float* __restrict__ W1s,
               const float* __restrict__ b1s,
               const float* __restrict__ W2s,
               const float* __restrict__ b2s,
               const float* __restrict__ epsp,
               int layer) {
    extern __shared__ char smc[];
    __half* sAhi = (__half*)(smc + SM_AHI);
    __half* sAlo = (__half*)(smc + SM_ALO);
    __half* sWT  = (__half*)(smc + SM_WT);

    int tid = threadIdx.x;
    int wid = tid >> 5, lane = tid & 31;
    int g = lane >> 2, ti = lane & 3;
    int row0 = blockIdx.x * 128;

    const float* zin = (layer == 0) ? xin : g_z;
    const float* W1 = W1s + layer * D * D;
    const float* W2 = W2s + layer * D * D;
    const float* b1 = b1s + layer * D;
    const float* b2 = b2s + layer * D;
    const float onePlusEps = 1.f + __ldg(&epsp[layer]);

    // Stage: A = h split (hi/lo); WT = W1 hi
    for (int idx = tid; idx < D * D; idx += 256) {
        int r = idx >> 7, k = idx & 127;
        int gr = row0 + r;
        float hv = 0.f;
        if (gr < N_NODES)
            hv = fmaf(onePlusEps, zin[(size_t)gr * D + k], g_agg[(size_t)gr * D + k]);
        __half hi = __float2half_rn(hv);
        sAhi[r * SA + k] = hi;
        sAlo[r * SA + k] = __float2half_rn(hv - __half2float(hi));
    }
    fill_wt(W1, sWT, tid, 0);
    __syncthreads();

    float C[16][4];
#pragma unroll
    for (int nt = 0; nt < 16; nt++)
#pragma unroll
        for (int j = 0; j < 4; j++) C[nt][j] = 0.f;

    // GEMM1: (Ahi + Alo) * W1hi
    gemm_pass<true>(sAhi, sAlo, sWT, C, wid, g, ti);
    __syncthreads();
    fill_wt(W1, sWT, tid, 1);                  // WT = W1 lo
    __syncthreads();
    gemm_pass<false>(sAhi, sAlo, sWT, C, wid, g, ti);   // + Ahi * W1lo
    __syncthreads();

    // Epilogue 1: T = relu(C + b1) -> A tiles (hi/lo); zero C
    {
        int r0 = wid * 16 + g;
#pragma unroll
        for (int nt = 0; nt < 16; nt++) {
            int c0 = nt * 8 + ti * 2;
            float bv0 = __ldg(&b1[c0]), bv1 = __ldg(&b1[c0 + 1]);
            float t00 = fmaxf(C[nt][0] + bv0, 0.f);
            float t01 = fmaxf(C[nt][1] + bv1, 0.f);
            float t10 = fmaxf(C[nt][2] + bv0, 0.f);
            float t11 = fmaxf(C[nt][3] + bv1, 0.f);
            uint32_t p0 = pack_halves(t00, t01);
            uint32_t p1 = pack_halves(t10, t11);
            *(uint32_t*)&sAhi[r0 * SA + c0] = p0;
            *(uint32_t*)&sAhi[(r0 + 8) * SA + c0] = p1;
            __half h00 = __ushort_as_half((unsigned short)(p0 & 0xFFFF));
            __half h01 = __ushort_as_half((unsigned short)(p0 >> 16));
            __half h10 = __ushort_as_half((unsigned short)(p1 & 0xFFFF));
            __half h11 = __ushort_as_half((unsigned short)(p1 >> 16));
            *(uint32_t*)&sAlo[r0 * SA + c0] =
                pack_halves(t00 - __half2float(h00), t01 - __half2float(h01));
            *(uint32_t*)&sAlo[(r0 + 8) * SA + c0] =
                pack_halves(t10 - __half2float(h10), t11 - __half2float(h11));
#pragma unroll
            for (int j = 0; j < 4; j++) C[nt][j] = 0.f;
        }
    }
    fill_wt(W2, sWT, tid, 0);                  // WT = W2 hi
    __syncthreads();

    // GEMM2: (Thi + Tlo) * W2hi
    gemm_pass<true>(sAhi, sAlo, sWT, C, wid, g, ti);
    __syncthreads();
    fill_wt(W2, sWT, tid, 1);                  // WT = W2 lo
    __syncthreads();
    gemm_pass<false>(sAhi, sAlo, sWT, C, wid, g, ti);   // + Thi * W2lo

    // Epilogue 2: z = relu(C + b2) -> g_z ; BN stats on layer 2
    float* sPartS = (float*)(smc + SM_ALO);    // 1024 floats (sAlo unused now)
    float* sPartQ = sPartS + 1024;
    {
        int lr = wid * 16 + g;
        int gr0 = row0 + lr, gr1 = gr0 + 8;
#pragma unroll
        for (int nt = 0; nt < 16; nt++) {
            int c0 = nt * 8 + ti * 2;
            float bv0 = __ldg(&b2[c0]), bv1 = __ldg(&b2[c0 + 1]);
            float v00 = fmaxf(C[nt][0] + bv0, 0.f);
            float v01 = fmaxf(C[nt][1] + bv1, 0.f);
            float v10 = fmaxf(C[nt][2] + bv0, 0.f);
            float v11 = fmaxf(C[nt][3] + bv1, 0.f);
            if (gr0 < N_NODES) {
                float2 t = make_float2(v00, v01);
                *(float2*)&g_z[(size_t)gr0 * D + c0] = t;
            } else { v00 = v01 = 0.f; }
            if (gr1 < N_NODES) {
                float2 t = make_float2(v10, v11);
                *(float2*)&g_z[(size_t)gr1 * D + c0] = t;
            } else { v10 = v11 = 0.f; }
            if (layer == 2) {
                float s0 = v00 + v10, s1 = v01 + v11;
                float q0 = v00 * v00 + v10 * v10, q1 = v01 * v01 + v11 * v11;
#pragma unroll
                for (int o = 4; o < 32; o <<= 1) {
                    s0 += __shfl_xor_sync(0xFFFFFFFFu, s0, o);
                    s1 += __shfl_xor_sync(0xFFFFFFFFu, s1, o);
                    q0 += __shfl_xor_sync(0xFFFFFFFFu, q0, o);
                    q1 += __shfl_xor_sync(0xFFFFFFFFu, q1, o);
                }
                if (lane < 4) {
                    sPartS[wid * 128 + c0] = s0;
                    sPartS[wid * 128 + c0 + 1] = s1;
                    sPartQ[wid * 128 + c0] = q0;
                    sPartQ[wid * 128 + c0 + 1] = q1;
                }
            }
        }
    }
    if (layer == 2) {
        __syncthreads();
        if (tid < 128) {
            float s = 0.f;
#pragma unroll
            for (int w = 0; w < 8; w++) s += sPartS[w * 128 + tid];
            atomicAdd(&g_stats[tid], s);
        } else {
            int c = tid - 128;
            float q = 0.f;
#pragma unroll
            for (int w = 0; w < 8; w++) q += sPartQ[w * 128 + c];
            atomicAdd(&g_stats[D + c], q);
        }
    }
}

// ===========================================================================
// Fused BN-normalize (zn out) + projection GEMM (HMMA split) + PReLU (p out)
// ===========================================================================
__global__ void __launch_bounds__(256)
proj_mma_kernel(const float* __restrict__ Wp,
                const float* __restrict__ bp,
                const float* __restrict__ gamma,
                const float* __restrict__ beta,
                const float* __restrict__ prelu_a,
                float* __restrict__ out) {
    extern __shared__ char smc[];
    __half* sAhi = (__half*)(smc + SM_AHI);
    __half* sAlo = (__half*)(smc + SM_ALO);
    __half* sWT  = (__half*)(smc + SM_WT);
    float* sScale = (float*)(smc + SM_SC);
    float* sShift = sScale + 128;

    int tid = threadIdx.x;
    int wid = tid >> 5, lane = tid & 31;
    int g = lane >> 2, ti = lane & 3;
    int row0 = blockIdx.x * 128;

    if (tid < D) {
        float mean = g_stats[tid] * (1.f / N_NODES);
        float var = g_stats[D + tid] * (1.f / N_NODES) - mean * mean;
        float rs = rsqrtf(var + BN_EPS);
        float sc = __ldg(&gamma[tid]) * rs;
        sScale[tid] = sc;
        sShift[tid] = __ldg(&beta[tid]) - mean * sc;
    }
    __syncthreads();

    float* zn_out = out;
    float* p_out = out + (size_t)N_NODES * D;

    // Stage: zn = z*scale+shift -> global zn + split tiles; WT = Wp hi
    for (int idx = tid; idx < D * D; idx += 256) {
        int r = idx >> 7, k = idx & 127;
        int gr = row0 + r;
        float zv = 0.f;
        if (gr < N_NODES) {
            zv = fmaf(g_z[(size_t)gr * D + k], sScale[k], sShift[k]);
            zn_out[(size_t)gr * D + k] = zv;
        }
        __half hi = __float2half_rn(zv);
        sAhi[r * SA + k] = hi;
        sAlo[r * SA + k] = __float2half_rn(zv - __half2float(hi));
    }
    fill_wt(Wp, sWT, tid, 0);
    __syncthreads();

    float C[16][4];
#pragma unroll
    for (int nt = 0; nt < 16; nt++)
#pragma unroll
        for (int j = 0; j < 4; j++) C[nt][j] = 0.f;

    gemm_pass<true>(sAhi, sAlo, sWT, C, wid, g, ti);
    __syncthreads();
    fill_wt(Wp, sWT, tid, 1);
    __syncthreads();
    gemm_pass<false>(sAhi, sAlo, sWT, C, wid, g, ti);

    {
        float a = __ldg(&prelu_a[0]);
        int lr = wid * 16 + g;
        int gr0 = row0 + lr, gr1 = gr0 + 8;
#pragma unroll
        for (int nt = 0; nt < 16; nt++) {
            int c0 = nt * 8 + ti * 2;
            float bv0 = __ldg(&bp[c0]), bv1 = __ldg(&bp[c0 + 1]);
            float v00 = C[nt][0] + bv0, v01 = C[nt][1] + bv1;
            float v10 = C[nt][2] + bv0, v11 = C[nt][3] + bv1;
            v00 = (v00 >= 0.f) ? v00 : a * v00;
            v01 = (v01 >= 0.f) ? v01 : a * v01;
            v10 = (v10 >= 0.f) ? v10 : a * v10;
            v11 = (v11 >= 0.f) ? v11 : a * v11;
            if (gr0 < N_NODES) {
                float2 t = make_float2(v00, v01);
                *(float2*)&p_out[(size_t)gr0 * D + c0] = t;
            }
            if (gr1 < N_NODES) {
                float2 t = make_float2(v10, v11);
                *(float2*)&p_out[(size_t)gr1 * D + c0] = t;
            }
        }
    }
}

// ---------------------------------------------------------------------------
extern "C" void kernel_launch(void* const* d_in, const int* in_sizes, int n_in,
                              void* d_out, int out_size) {
    const float* x       = (const float*)d_in[0];
    const float* ew      = (const float*)d_in[1];
    const float* W1s     = (const float*)d_in[2];
    const float* b1s     = (const float*)d_in[3];
    const float* W2s     = (const float*)d_in[4];
    const float* b2s     = (const float*)d_in[5];
    const float* eps     = (const float*)d_in[6];
    const float* gamma   = (const float*)d_in[7];
    const float* beta    = (const float*)d_in[8];
    const float* Wp      = (const float*)d_in[9];
    const float* bp      = (const float*)d_in[10];
    const float* prelu_a = (const float*)d_in[11];
    const int*   ei32    = (const int*)d_in[12];
    float* out = (float*)d_out;

    cudaFuncSetAttribute(mlp_mma_kernel, cudaFuncAttributeMaxDynamicSharedMemorySize, SM_MLP_TOTAL);
    cudaFuncSetAttribute(proj_mma_kernel, cudaFuncAttributeMaxDynamicSharedMemorySize, SM_PROJ_TOTAL);

    const int edgeBlocks = (N_EDGES + 255) / 256;           // 3125
    const int mmaBlocks  = (N_NODES + 127) / 128;           // 391
    const int aggBlocks  = (N_NODES * 32 + 255) / 256;      // 6250
    const int nodeBlocks = (N_NODES + 255) / 256;           // 196

    zero_counters_kernel<<<nodeBlocks, 256>>>(ei32);
    hist_kernel<<<edgeBlocks, 256>>>(ei32);
    scan_partial_kernel<<<N_CHUNKS, SCAN_CHUNK>>>();
    scan_part_kernel<<<1, 128>>>();
    scan_add_kernel<<<nodeBlocks, 256>>>();
    scatter_kernel<<<edgeBlocks, 256>>>(ew, ei32);

    for (int l = 0; l < 3; l++) {
        agg_kernel<<<aggBlocks, 256>>>(x, l == 0 ? 1 : 0);
        mlp_mma_kernel<<<mmaBlocks, 256, SM_MLP_TOTAL>>>(x, W1s, b1s, W2s, b2s, eps, l);
    }
    proj_mma_kernel<<<mmaBlocks, 256, SM_PROJ_TOTAL>>>(Wp, bp, gamma, beta, prelu_a, out);
}